// round 3
// baseline (speedup 1.0000x reference)
#include <cuda_runtime.h>
#include <math.h>
#include <stdint.h>

#define N_NODES 10000
#define N_EDGES 640000
#define D_IN    256
#define D_H1    64
#define D_H2    32
#define D_OUT   16

// ---------------- scratch (device globals; no allocation allowed) ------------
__device__ float g_h [N_NODES * D_IN];   // relu(x @ emb)          [10000,256]
__device__ float g_t1[N_NODES * D_H1];   // h @ W1 / relu'd agg1   [10000,64]
__device__ float g_a1[N_NODES * D_H1];   // aggregation buffer 1
__device__ float g_t2[N_NODES * D_H2];   // t1 @ W2 / relu'd agg2  [10000,32]
__device__ float g_a2[N_NODES * D_H2];   // aggregation buffer 2
__device__ int   g_src[N_EDGES];
__device__ int   g_dst[N_EDGES];
__device__ int   g_deg [N_NODES];
__device__ float g_dinv[N_NODES];
__device__ int   g_is64;

// ---------------- edge index dtype detection + decode ------------------------
__global__ void k_detect(const void* __restrict__ ei) {
    if (threadIdx.x == 0 && blockIdx.x == 0) {
        const long long* p = (const long long*)ei;
        int ok = 1;
        for (int i = 0; i < 16; i++) {
            long long v = p[i];
            if (v < 0 || v >= N_NODES) ok = 0;
        }
        g_is64 = ok;
    }
}

__global__ void k_decode(const void* __restrict__ ei) {
    int e = blockIdx.x * blockDim.x + threadIdx.x;
    if (e >= N_EDGES) return;
    if (g_is64) {
        const long long* p = (const long long*)ei;
        g_src[e] = (int)p[e];
        g_dst[e] = (int)p[N_EDGES + e];
    } else {
        const int* p = (const int*)ei;
        g_src[e] = p[e];
        g_dst[e] = p[N_EDGES + e];
    }
}

// ---------------- degree / normalization ------------------------------------
__global__ void k_zero_deg() {
    int i = blockIdx.x * blockDim.x + threadIdx.x;
    if (i < N_NODES) g_deg[i] = 0;
}

__global__ void k_count_deg() {
    int e = blockIdx.x * blockDim.x + threadIdx.x;
    if (e < N_EDGES) atomicAdd(&g_deg[g_dst[e]], 1);
}

__global__ void k_dinv() {
    int i = blockIdx.x * blockDim.x + threadIdx.x;
    if (i < N_NODES) {
        // +1 for the self loop; deg >= 1 always
        g_dinv[i] = rsqrtf((float)(g_deg[i] + 1));
    }
}

// ---------------- GEMM1: h = relu(x @ emb)  M=10000 K=10000 N=256 ------------
#define BM 128
#define BN 64
#define BK 16

__global__ __launch_bounds__(256)
void k_gemm1_relu(const float* __restrict__ A,   // [10000,10000]
                  const float* __restrict__ B)   // [10000,256]
{
    __shared__ float As[BK][BM];
    __shared__ float Bs[BK][BN];

    const int t  = threadIdx.x;
    const int m0 = blockIdx.x * BM;
    const int n0 = blockIdx.y * BN;
    const int tx = t & 15;   // 0..15 -> 4 cols each
    const int ty = t >> 4;   // 0..15 -> 8 rows each

    float acc[8][4];
#pragma unroll
    for (int i = 0; i < 8; i++)
#pragma unroll
        for (int j = 0; j < 4; j++) acc[i][j] = 0.0f;

    const int br = t >> 4;        // 0..15 (B tile row)
    const int bc = t & 15;        // 0..15 (B tile float4 col)

    for (int k0 = 0; k0 < N_NODES; k0 += BK) {
        // load A tile (transposed into smem)
#pragma unroll
        for (int i = 0; i < 2; i++) {
            int f   = t + i * 256;
            int row = f >> 2;         // 0..127
            int cv  = f & 3;          // 0..3
            int gm  = m0 + row;
            float4 v = make_float4(0.f, 0.f, 0.f, 0.f);
            if (gm < N_NODES)
                v = *(const float4*)&A[(size_t)gm * N_NODES + k0 + cv * 4];
            As[cv * 4 + 0][row] = v.x;
            As[cv * 4 + 1][row] = v.y;
            As[cv * 4 + 2][row] = v.z;
            As[cv * 4 + 3][row] = v.w;
        }
        // load B tile
        {
            float4 v = *(const float4*)&B[(size_t)(k0 + br) * D_IN + n0 + bc * 4];
            *(float4*)&Bs[br][bc * 4] = v;
        }
        __syncthreads();

#pragma unroll
        for (int kk = 0; kk < BK; kk++) {
            float a[8], b[4];
#pragma unroll
            for (int i = 0; i < 8; i++) a[i] = As[kk][ty * 8 + i];
#pragma unroll
            for (int j = 0; j < 4; j++) b[j] = Bs[kk][tx * 4 + j];
#pragma unroll
            for (int i = 0; i < 8; i++)
#pragma unroll
                for (int j = 0; j < 4; j++)
                    acc[i][j] = fmaf(a[i], b[j], acc[i][j]);
        }
        __syncthreads();
    }

#pragma unroll
    for (int i = 0; i < 8; i++) {
        int gm = m0 + ty * 8 + i;
        if (gm < N_NODES) {
#pragma unroll
            for (int j = 0; j < 4; j++) {
                int gn = n0 + tx * 4 + j;
                g_h[(size_t)gm * D_IN + gn] = fmaxf(acc[i][j], 0.0f);
            }
        }
    }
}

// ---------------- small dense linears: Y = X @ W -----------------------------
template <int IN, int OUT>
__global__ void k_linear(const float* __restrict__ X,
                         const float* __restrict__ W,
                         float* __restrict__ Y)
{
    int col = threadIdx.x;                               // 0..OUT-1
    int row = blockIdx.x * blockDim.y + threadIdx.y;
    if (row >= N_NODES) return;
    const float* xr = X + (size_t)row * IN;
    float acc = 0.0f;
#pragma unroll 8
    for (int k = 0; k < IN; k++)
        acc = fmaf(xr[k], W[k * OUT + col], acc);
    Y[(size_t)row * OUT + col] = acc;
}

// ---------------- GCN aggregation --------------------------------------------
// init: self-loop contribution  acc[i] = x[i] * dinv[i]^2
template <int F>
__global__ void k_agg_init(const float* __restrict__ X, float* __restrict__ Acc)
{
    int f = threadIdx.x;
    int i = blockIdx.x * blockDim.y + threadIdx.y;
    if (i >= N_NODES) return;
    float di = g_dinv[i];
    Acc[(size_t)i * F + f] = X[(size_t)i * F + f] * di * di;
}

// edges: acc[d] += x[s] * dinv[s]*dinv[d]
template <int F>
__global__ void k_agg_edges(const float* __restrict__ X,
                            float* __restrict__ Acc)
{
    int f = threadIdx.x;
    int e = blockIdx.x * blockDim.y + threadIdx.y;
    if (e >= N_EDGES) return;
    int s = g_src[e];
    int d = g_dst[e];
    float norm = g_dinv[s] * g_dinv[d];
    atomicAdd(&Acc[(size_t)d * F + f], X[(size_t)s * F + f] * norm);
}

// finish: y = relu(acc + b)
template <int F>
__global__ void k_agg_finish(const float* __restrict__ Acc,
                             const float* __restrict__ bias,
                             float* __restrict__ Y)
{
    int f = threadIdx.x;
    int i = blockIdx.x * blockDim.y + threadIdx.y;
    if (i >= N_NODES) return;
    Y[(size_t)i * F + f] = fmaxf(Acc[(size_t)i * F + f] + bias[f], 0.0f);
}

// ---------------- launch -----------------------------------------------------
extern "C" void kernel_launch(void* const* d_in, const int* in_sizes, int n_in,
                              void* d_out, int out_size)
{
    const float* x    = (const float*)d_in[0];   // [10000,10000]
    const void*  ei   = d_in[1];                 // [2,640000] int32 or int64
    const float* emb  = (const float*)d_in[2];   // [10000,256]
    const float* W1   = (const float*)d_in[3];   // [256,64]
    const float* b1   = (const float*)d_in[4];   // [64]
    const float* W2   = (const float*)d_in[5];   // [64,32]
    const float* b2   = (const float*)d_in[6];   // [32]
    const float* decW = (const float*)d_in[7];   // [32,16]
    float*       out  = (float*)d_out;           // [10000,16]

    float *gh, *gt1, *ga1, *gt2, *ga2;
    cudaGetSymbolAddress((void**)&gh,  g_h);
    cudaGetSymbolAddress((void**)&gt1, g_t1);
    cudaGetSymbolAddress((void**)&ga1, g_a1);
    cudaGetSymbolAddress((void**)&gt2, g_t2);
    cudaGetSymbolAddress((void**)&ga2, g_a2);

    // edge decode (dtype-robust) + degree + normalization
    k_detect<<<1, 32>>>(ei);
    k_decode<<<(N_EDGES + 255) / 256, 256>>>(ei);
    k_zero_deg<<<(N_NODES + 255) / 256, 256>>>();
    k_count_deg<<<(N_EDGES + 255) / 256, 256>>>();
    k_dinv<<<(N_NODES + 255) / 256, 256>>>();

    // h = relu(x @ emb)
    {
        dim3 grid((N_NODES + BM - 1) / BM, D_IN / BN);
        k_gemm1_relu<<<grid, 256>>>(x, emb);
    }

    // layer 1: t1 = h @ W1 ; agg ; relu(+b1)
    {
        dim3 blk(D_H1, 256 / D_H1);
        k_linear<D_IN, D_H1><<<(N_NODES + blk.y - 1) / blk.y, blk>>>(gh, W1, gt1);
        k_agg_init<D_H1><<<(N_NODES + blk.y - 1) / blk.y, blk>>>(gt1, ga1);
        k_agg_edges<D_H1><<<(N_EDGES + blk.y - 1) / blk.y, blk>>>(gt1, ga1);
        k_agg_finish<D_H1><<<(N_NODES + blk.y - 1) / blk.y, blk>>>(ga1, b1, gt1);
    }

    // layer 2: t2 = t1 @ W2 ; agg ; relu(+b2)
    {
        dim3 blk(D_H2, 256 / D_H2);
        k_linear<D_H1, D_H2><<<(N_NODES + blk.y - 1) / blk.y, blk>>>(gt1, W2, gt2);
        k_agg_init<D_H2><<<(N_NODES + blk.y - 1) / blk.y, blk>>>(gt2, ga2);
        k_agg_edges<D_H2><<<(N_EDGES + blk.y - 1) / blk.y, blk>>>(gt2, ga2);
        k_agg_finish<D_H2><<<(N_NODES + blk.y - 1) / blk.y, blk>>>(ga2, b2, gt2);
    }

    // decoder: out = t2 @ dec_W
    {
        dim3 blk(D_OUT, 256 / D_OUT);
        k_linear<D_H2, D_OUT><<<(N_NODES + blk.y - 1) / blk.y, blk>>>(gt2, decW, out);
    }
}

// round 4
// speedup vs baseline: 2.4802x; 2.4802x over previous
#include <cuda_runtime.h>
#include <math.h>
#include <stdint.h>

#define N_NODES 10000
#define N_EDGES 640000
#define D_IN    256
#define D_H1    64
#define D_H2    32
#define D_OUT   16

// ---------------- scratch (device globals; no allocation allowed) ------------
__device__ float g_h [N_NODES * D_IN];
__device__ float g_t1[N_NODES * D_H1];
__device__ float g_a1[N_NODES * D_H1];
__device__ float g_t2[N_NODES * D_H2];
__device__ float g_a2[N_NODES * D_H2];
__device__ int   g_src[N_EDGES];
__device__ int   g_dst[N_EDGES];
__device__ int   g_deg [N_NODES];
__device__ float g_dinv[N_NODES];
__device__ int   g_is64;

// ---------------- edge index dtype detection + decode ------------------------
__global__ void k_detect(const void* __restrict__ ei) {
    if (threadIdx.x == 0 && blockIdx.x == 0) {
        const long long* p = (const long long*)ei;
        int ok = 1;
        for (int i = 0; i < 16; i++) {
            long long v = p[i];
            if (v < 0 || v >= N_NODES) ok = 0;
        }
        g_is64 = ok;
    }
}

__global__ void k_decode(const void* __restrict__ ei) {
    int e = blockIdx.x * blockDim.x + threadIdx.x;
    if (e >= N_EDGES) return;
    if (g_is64) {
        const long long* p = (const long long*)ei;
        g_src[e] = (int)p[e];
        g_dst[e] = (int)p[N_EDGES + e];
    } else {
        const int* p = (const int*)ei;
        g_src[e] = p[e];
        g_dst[e] = p[N_EDGES + e];
    }
}

// ---------------- degree / normalization ------------------------------------
__global__ void k_zero_deg() {
    int i = blockIdx.x * blockDim.x + threadIdx.x;
    if (i < N_NODES) g_deg[i] = 0;
}

__global__ void k_count_deg() {
    int e = blockIdx.x * blockDim.x + threadIdx.x;
    if (e < N_EDGES) atomicAdd(&g_deg[g_dst[e]], 1);
}

__global__ void k_dinv() {
    int i = blockIdx.x * blockDim.x + threadIdx.x;
    if (i < N_NODES) g_dinv[i] = rsqrtf((float)(g_deg[i] + 1));
}

// ---------------- GEMM1 (tensor cores, tf32): h = relu(x @ emb) --------------
// M=10000 K=10000 N=256.  BM=160 BN=128 BK=16, 320 threads (10 warps: 5M x 2N)
// warp tile 32x64 = 2(M) x 8(N) mma tiles of m16n8k8.
// grid = 63 x 2 = 126 blocks -> one full wave on 148 SMs.

#define GBM 160
#define GBN 128
#define GBK 16
#define LDA_S 20    // BK + 4  (fragment loads conflict-free)
#define LDB_S 136   // BN + 8

__device__ __forceinline__ float to_tf32(float x) {
    float y;
    asm("cvt.rna.tf32.f32 %0, %1;" : "=f"(y) : "f"(x));
    return y;
}

__device__ __forceinline__ void mma_tf32(float* c, const uint32_t* a, const uint32_t* b) {
    asm volatile(
        "mma.sync.aligned.m16n8k8.row.col.f32.tf32.tf32.f32 "
        "{%0,%1,%2,%3}, {%4,%5,%6,%7}, {%8,%9}, {%0,%1,%2,%3};"
        : "+f"(c[0]), "+f"(c[1]), "+f"(c[2]), "+f"(c[3])
        : "r"(a[0]), "r"(a[1]), "r"(a[2]), "r"(a[3]), "r"(b[0]), "r"(b[1]));
}

__global__ __launch_bounds__(320, 1)
void k_gemm1_tf32(const float* __restrict__ A,   // [10000,10000]
                  const float* __restrict__ B)   // [10000,256]
{
    __shared__ float As[2][GBM * LDA_S];   // [m][k] padded
    __shared__ float Bs[2][GBK * LDB_S];   // [k][n] padded

    const int tid  = threadIdx.x;
    const int lane = tid & 31;
    const int wid  = tid >> 5;
    const int wm   = wid % 5;       // 0..4  (M)
    const int wn   = wid / 5;       // 0..1  (N)
    const int m0   = blockIdx.x * GBM;
    const int n0   = blockIdx.y * GBN;

    float acc[2][8][4];
#pragma unroll
    for (int mi = 0; mi < 2; mi++)
#pragma unroll
        for (int ni = 0; ni < 8; ni++)
#pragma unroll
            for (int r = 0; r < 4; r++) acc[mi][ni][r] = 0.0f;

    // A tile: 160 rows x 4 float4 = 640 f4 -> 2 per thread
    // B tile: 16 rows x 32 float4 = 512 f4 -> 1 or 2 per thread
    float4 pa[2], pb[2];
    int a_row[2], a_cv[2];
#pragma unroll
    for (int i = 0; i < 2; i++) {
        int f = tid + i * 320;
        a_row[i] = f >> 2;
        a_cv[i]  = f & 3;
    }
    const int b_f1 = tid;          // always valid (<512)
    const int b_f2 = tid + 320;    // valid if < 512
    const int b_r1 = b_f1 >> 5, b_c1 = b_f1 & 31;
    const int b_r2 = b_f2 >> 5, b_c2 = b_f2 & 31;
    const bool b_has2 = (b_f2 < 512);

    auto prefetch = [&](int k0) {
#pragma unroll
        for (int i = 0; i < 2; i++) {
            int gm = m0 + a_row[i];
            if (gm < N_NODES)
                pa[i] = *(const float4*)&A[(size_t)gm * N_NODES + k0 + a_cv[i] * 4];
            else
                pa[i] = make_float4(0.f, 0.f, 0.f, 0.f);
        }
        pb[0] = *(const float4*)&B[(size_t)(k0 + b_r1) * D_IN + n0 + b_c1 * 4];
        if (b_has2)
            pb[1] = *(const float4*)&B[(size_t)(k0 + b_r2) * D_IN + n0 + b_c2 * 4];
    };

    auto store = [&](int buf) {
#pragma unroll
        for (int i = 0; i < 2; i++) {
            float* p = &As[buf][a_row[i] * LDA_S + a_cv[i] * 4];
            p[0] = to_tf32(pa[i].x);
            p[1] = to_tf32(pa[i].y);
            p[2] = to_tf32(pa[i].z);
            p[3] = to_tf32(pa[i].w);
        }
        {
            float* p = &Bs[buf][b_r1 * LDB_S + b_c1 * 4];
            p[0] = to_tf32(pb[0].x); p[1] = to_tf32(pb[0].y);
            p[2] = to_tf32(pb[0].z); p[3] = to_tf32(pb[0].w);
        }
        if (b_has2) {
            float* p = &Bs[buf][b_r2 * LDB_S + b_c2 * 4];
            p[0] = to_tf32(pb[1].x); p[1] = to_tf32(pb[1].y);
            p[2] = to_tf32(pb[1].z); p[3] = to_tf32(pb[1].w);
        }
    };

    auto compute = [&](int buf) {
#pragma unroll
        for (int ks = 0; ks < 2; ks++) {
            const int kb = ks * 8;
            uint32_t a[2][4], b[8][2];
#pragma unroll
            for (int mi = 0; mi < 2; mi++) {
                int idx = (wm * 32 + mi * 16 + (lane >> 2)) * LDA_S + kb + (lane & 3);
                a[mi][0] = __float_as_uint(As[buf][idx]);
                a[mi][1] = __float_as_uint(As[buf][idx + 8 * LDA_S]);
                a[mi][2] = __float_as_uint(As[buf][idx + 4]);
                a[mi][3] = __float_as_uint(As[buf][idx + 8 * LDA_S + 4]);
            }
#pragma unroll
            for (int ni = 0; ni < 8; ni++) {
                int idx = (kb + (lane & 3)) * LDB_S + wn * 64 + ni * 8 + (lane >> 2);
                b[ni][0] = __float_as_uint(Bs[buf][idx]);
                b[ni][1] = __float_as_uint(Bs[buf][idx + 4 * LDB_S]);
            }
#pragma unroll
            for (int mi = 0; mi < 2; mi++)
#pragma unroll
                for (int ni = 0; ni < 8; ni++)
                    mma_tf32(acc[mi][ni], a[mi], b[ni]);
        }
    };

    const int NIT = N_NODES / GBK;   // 625
    prefetch(0);
    store(0);
    __syncthreads();

    for (int it = 0; it < NIT; ++it) {
        int buf = it & 1;
        if (it + 1 < NIT) prefetch((it + 1) * GBK);
        compute(buf);
        if (it + 1 < NIT) {
            store(buf ^ 1);
            __syncthreads();
        }
    }

    // epilogue: relu + store to g_h
#pragma unroll
    for (int mi = 0; mi < 2; mi++) {
        int row0 = m0 + wm * 32 + mi * 16 + (lane >> 2);
#pragma unroll
        for (int ni = 0; ni < 8; ni++) {
            int col = n0 + wn * 64 + ni * 8 + 2 * (lane & 3);
            if (row0 < N_NODES) {
                float2 v = make_float2(fmaxf(acc[mi][ni][0], 0.f),
                                       fmaxf(acc[mi][ni][1], 0.f));
                *(float2*)&g_h[(size_t)row0 * D_IN + col] = v;
            }
            if (row0 + 8 < N_NODES) {
                float2 v = make_float2(fmaxf(acc[mi][ni][2], 0.f),
                                       fmaxf(acc[mi][ni][3], 0.f));
                *(float2*)&g_h[(size_t)(row0 + 8) * D_IN + col] = v;
            }
        }
    }
}

// ---------------- small dense linears: Y = X @ W -----------------------------
template <int IN, int OUT>
__global__ void k_linear(const float* __restrict__ X,
                         const float* __restrict__ W,
                         float* __restrict__ Y)
{
    int col = threadIdx.x;
    int row = blockIdx.x * blockDim.y + threadIdx.y;
    if (row >= N_NODES) return;
    const float* xr = X + (size_t)row * IN;
    float acc = 0.0f;
#pragma unroll 8
    for (int k = 0; k < IN; k++)
        acc = fmaf(xr[k], W[k * OUT + col], acc);
    Y[(size_t)row * OUT + col] = acc;
}

// ---------------- GCN aggregation --------------------------------------------
template <int F>
__global__ void k_agg_init(const float* __restrict__ X, float* __restrict__ Acc)
{
    int f = threadIdx.x;
    int i = blockIdx.x * blockDim.y + threadIdx.y;
    if (i >= N_NODES) return;
    float di = g_dinv[i];
    Acc[(size_t)i * F + f] = X[(size_t)i * F + f] * di * di;
}

template <int F>
__global__ void k_agg_edges(const float* __restrict__ X,
                            float* __restrict__ Acc)
{
    int f = threadIdx.x;
    int e = blockIdx.x * blockDim.y + threadIdx.y;
    if (e >= N_EDGES) return;
    int s = g_src[e];
    int d = g_dst[e];
    float norm = g_dinv[s] * g_dinv[d];
    atomicAdd(&Acc[(size_t)d * F + f], X[(size_t)s * F + f] * norm);
}

template <int F>
__global__ void k_agg_finish(const float* __restrict__ Acc,
                             const float* __restrict__ bias,
                             float* __restrict__ Y)
{
    int f = threadIdx.x;
    int i = blockIdx.x * blockDim.y + threadIdx.y;
    if (i >= N_NODES) return;
    Y[(size_t)i * F + f] = fmaxf(Acc[(size_t)i * F + f] + bias[f], 0.0f);
}

// ---------------- launch -----------------------------------------------------
extern "C" void kernel_launch(void* const* d_in, const int* in_sizes, int n_in,
                              void* d_out, int out_size)
{
    const float* x    = (const float*)d_in[0];
    const void*  ei   = d_in[1];
    const float* emb  = (const float*)d_in[2];
    const float* W1   = (const float*)d_in[3];
    const float* b1   = (const float*)d_in[4];
    const float* W2   = (const float*)d_in[5];
    const float* b2   = (const float*)d_in[6];
    const float* decW = (const float*)d_in[7];
    float*       out  = (float*)d_out;

    float *gh, *gt1, *ga1, *gt2, *ga2;
    cudaGetSymbolAddress((void**)&gh,  g_h);
    cudaGetSymbolAddress((void**)&gt1, g_t1);
    cudaGetSymbolAddress((void**)&ga1, g_a1);
    cudaGetSymbolAddress((void**)&gt2, g_t2);
    cudaGetSymbolAddress((void**)&ga2, g_a2);

    k_detect<<<1, 32>>>(ei);
    k_decode<<<(N_EDGES + 255) / 256, 256>>>(ei);
    k_zero_deg<<<(N_NODES + 255) / 256, 256>>>();
    k_count_deg<<<(N_EDGES + 255) / 256, 256>>>();
    k_dinv<<<(N_NODES + 255) / 256, 256>>>();

    // h = relu(x @ emb)  — tf32 tensor cores
    {
        dim3 grid((N_NODES + GBM - 1) / GBM, D_IN / GBN);   // 63 x 2
        k_gemm1_tf32<<<grid, 320>>>(x, emb);
    }

    // layer 1
    {
        dim3 blk(D_H1, 256 / D_H1);
        k_linear<D_IN, D_H1><<<(N_NODES + blk.y - 1) / blk.y, blk>>>(gh, W1, gt1);
        k_agg_init<D_H1><<<(N_NODES + blk.y - 1) / blk.y, blk>>>(gt1, ga1);
        k_agg_edges<D_H1><<<(N_EDGES + blk.y - 1) / blk.y, blk>>>(gt1, ga1);
        k_agg_finish<D_H1><<<(N_NODES + blk.y - 1) / blk.y, blk>>>(ga1, b1, gt1);
    }

    // layer 2
    {
        dim3 blk(D_H2, 256 / D_H2);
        k_linear<D_H1, D_H2><<<(N_NODES + blk.y - 1) / blk.y, blk>>>(gt1, W2, gt2);
        k_agg_init<D_H2><<<(N_NODES + blk.y - 1) / blk.y, blk>>>(gt2, ga2);
        k_agg_edges<D_H2><<<(N_EDGES + blk.y - 1) / blk.y, blk>>>(gt2, ga2);
        k_agg_finish<D_H2><<<(N_NODES + blk.y - 1) / blk.y, blk>>>(ga2, b2, gt2);
    }

    // decoder
    {
        dim3 blk(D_OUT, 256 / D_OUT);
        k_linear<D_H2, D_OUT><<<(N_NODES + blk.y - 1) / blk.y, blk>>>(gt2, decW, out);
    }
}

// round 7
// speedup vs baseline: 3.5209x; 1.4196x over previous
#include <cuda_runtime.h>
#include <cuda_fp16.h>
#include <math.h>
#include <stdint.h>

#define N_NODES 10000
#define N_EDGES 640000
#define D_IN    256
#define D_H1    64
#define D_H2    32
#define D_OUT   16

// ---------------- scratch (device globals; no allocation allowed) ------------
__device__ float g_h [N_NODES * D_IN];
__device__ float g_t1[N_NODES * D_H1];
__device__ float g_a1[N_NODES * D_H1];
__device__ float g_t2[N_NODES * D_H2];
__device__ float g_a2[N_NODES * D_H2];
__device__ int   g_src[N_EDGES];
__device__ int   g_dst[N_EDGES];
__device__ int   g_deg [N_NODES];
__device__ float g_dinv[N_NODES];
__device__ int   g_is64;

// ---------------- edge index dtype detection + decode (+deg count) -----------
__global__ void k_detect(const void* __restrict__ ei) {
    if (threadIdx.x == 0 && blockIdx.x == 0) {
        const long long* p = (const long long*)ei;
        int ok = 1;
        for (int i = 0; i < 16; i++) {
            long long v = p[i];
            if (v < 0 || v >= N_NODES) ok = 0;
        }
        g_is64 = ok;
    }
}

__global__ void k_decode_deg(const void* __restrict__ ei) {
    int e = blockIdx.x * blockDim.x + threadIdx.x;
    if (e >= N_EDGES) return;
    int s, d;
    if (g_is64) {
        const long long* p = (const long long*)ei;
        s = (int)p[e]; d = (int)p[N_EDGES + e];
    } else {
        const int* p = (const int*)ei;
        s = p[e]; d = p[N_EDGES + e];
    }
    g_src[e] = s;
    g_dst[e] = d;
    atomicAdd(&g_deg[d], 1);
}

__global__ void k_dinv() {
    int i = blockIdx.x * blockDim.x + threadIdx.x;
    if (i < N_NODES) g_dinv[i] = rsqrtf((float)(g_deg[i] + 1));
}

// ---------------- GEMM1 (fp16 HMMA): h = relu(x @ emb) ------------------------
// M=10000 K=10000 N=256. BM=128 BN=256(full) BK=32, 512 threads.
// 16 warps = 4(M) x 4(N); warp tile 32x64 = 2 x 8 mma m16n8k16.
// A converted fp32->fp16 in-register; ldmatrix fragment loads; 79 CTAs = 1 wave.

#define HBK 32
#define LDA_H 40     // A smem stride in halfs (conflict-free for ldmatrix)
#define LDB_H 264    // B smem stride in halfs
#define AS_BUF (128 * LDA_H)          // 5120 halfs per buffer
#define BS_BUF (HBK * LDB_H)          // 8448 halfs per buffer
#define GEMM_SMEM ((2 * AS_BUF + 2 * BS_BUF) * 2)   // 54272 bytes
#define KT 313     // ceil(10000/32)

__device__ __forceinline__ uint32_t smem_u32(const void* p) {
    uint32_t a;
    asm("{ .reg .u64 t; cvta.to.shared.u64 t, %1; cvt.u32.u64 %0, t; }"
        : "=r"(a) : "l"(p));
    return a;
}
__device__ __forceinline__ void ldsm4(uint32_t* r, uint32_t addr) {
    asm volatile("ldmatrix.sync.aligned.m8n8.x4.shared.b16 {%0,%1,%2,%3}, [%4];"
                 : "=r"(r[0]), "=r"(r[1]), "=r"(r[2]), "=r"(r[3]) : "r"(addr));
}
__device__ __forceinline__ void ldsm4t(uint32_t* r, uint32_t addr) {
    asm volatile("ldmatrix.sync.aligned.m8n8.x4.trans.shared.b16 {%0,%1,%2,%3}, [%4];"
                 : "=r"(r[0]), "=r"(r[1]), "=r"(r[2]), "=r"(r[3]) : "r"(addr));
}
__device__ __forceinline__ void mma_f16(float* c, const uint32_t* a, uint32_t b0, uint32_t b1) {
    asm volatile(
        "mma.sync.aligned.m16n8k16.row.col.f32.f16.f16.f32 "
        "{%0,%1,%2,%3}, {%4,%5,%6,%7}, {%8,%9}, {%0,%1,%2,%3};"
        : "+f"(c[0]), "+f"(c[1]), "+f"(c[2]), "+f"(c[3])
        : "r"(a[0]), "r"(a[1]), "r"(a[2]), "r"(a[3]), "r"(b0), "r"(b1));
}

__global__ __launch_bounds__(512, 1)
void k_gemm1_f16(const float* __restrict__ A,   // x   [10000,10000]
                 const float* __restrict__ B)   // emb [10000,256]
{
    extern __shared__ __half sm[];
    __half* As = sm;                 // [2][128][LDA_H]
    __half* Bs = sm + 2 * AS_BUF;    // [2][HBK][LDB_H]

    const int tid  = threadIdx.x;
    const int lane = tid & 31;
    const int wid  = tid >> 5;
    const int wm   = wid & 3;        // 0..3
    const int wn   = wid >> 2;       // 0..3
    const int m0   = blockIdx.x * 128;
    const uint32_t sbase = smem_u32(sm);

    float acc[2][8][4];
#pragma unroll
    for (int mi = 0; mi < 2; mi++)
#pragma unroll
        for (int ni = 0; ni < 8; ni++)
#pragma unroll
            for (int r = 0; r < 4; r++) acc[mi][ni][r] = 0.0f;

    // A tile: 128 rows x 8 f4 = 1024 f4 -> 2/thread.  B: 32 x 64 f4 = 2048 -> 4/thread.
    int a_row[2], a_c4[2];
#pragma unroll
    for (int i = 0; i < 2; i++) {
        int f = tid + i * 512;
        a_row[i] = f >> 3;  a_c4[i] = f & 7;
    }
    int b_row[4], b_c4[4];
#pragma unroll
    for (int i = 0; i < 4; i++) {
        int f = tid + i * 512;
        b_row[i] = f >> 6;  b_c4[i] = f & 63;
    }

    float4 pa[2], pb[4];

    auto prefetch = [&](int k0) {
#pragma unroll
        for (int i = 0; i < 2; i++) {
            int gm = m0 + a_row[i];
            int gk = k0 + a_c4[i] * 4;
            if (gm < N_NODES && gk < N_NODES)
                pa[i] = *(const float4*)&A[(size_t)gm * N_NODES + gk];
            else
                pa[i] = make_float4(0.f, 0.f, 0.f, 0.f);
        }
#pragma unroll
        for (int i = 0; i < 4; i++) {
            int gk = k0 + b_row[i];
            if (gk < N_NODES)
                pb[i] = *(const float4*)&B[(size_t)gk * D_IN + b_c4[i] * 4];
            else
                pb[i] = make_float4(0.f, 0.f, 0.f, 0.f);
        }
    };

    auto store = [&](int buf) {
#pragma unroll
        for (int i = 0; i < 2; i++) {
            __half* p = &As[buf * AS_BUF + a_row[i] * LDA_H + a_c4[i] * 4];
            *(half2*)(p)     = __floats2half2_rn(pa[i].x, pa[i].y);
            *(half2*)(p + 2) = __floats2half2_rn(pa[i].z, pa[i].w);
        }
#pragma unroll
        for (int i = 0; i < 4; i++) {
            __half* p = &Bs[buf * BS_BUF + b_row[i] * LDB_H + b_c4[i] * 4];
            *(half2*)(p)     = __floats2half2_rn(pb[i].x, pb[i].y);
            *(half2*)(p + 2) = __floats2half2_rn(pb[i].z, pb[i].w);
        }
    };

    // per-lane invariant ldmatrix address pieces (bytes)
    const uint32_t a_lane_off = ((lane & 15) * LDA_H + (lane >> 4) * 8) * 2;
    const uint32_t b_lane_off = ((lane & 15) * LDB_H + (lane >> 4) * 8) * 2;

    auto compute = [&](int buf) {
        const uint32_t abase = sbase + buf * (AS_BUF * 2);
        const uint32_t bbase = sbase + (2 * AS_BUF + buf * BS_BUF) * 2;
#pragma unroll
        for (int ks = 0; ks < 2; ks++) {
            uint32_t a[2][4], b[4][4];
#pragma unroll
            for (int mi = 0; mi < 2; mi++)
                ldsm4(a[mi], abase + a_lane_off +
                             ((wm * 32 + mi * 16) * LDA_H + ks * 16) * 2);
#pragma unroll
            for (int g = 0; g < 4; g++)
                ldsm4t(b[g], bbase + b_lane_off +
                             (ks * 16 * LDB_H + wn * 64 + g * 16) * 2);
#pragma unroll
            for (int mi = 0; mi < 2; mi++)
#pragma unroll
                for (int g = 0; g < 4; g++) {
                    mma_f16(acc[mi][g * 2 + 0], a[mi], b[g][0], b[g][1]);
                    mma_f16(acc[mi][g * 2 + 1], a[mi], b[g][2], b[g][3]);
                }
        }
    };

    prefetch(0);
    store(0);
    __syncthreads();

    for (int it = 0; it < KT; ++it) {
        int buf = it & 1;
        if (it + 1 < KT) prefetch((it + 1) * HBK);
        compute(buf);
        if (it + 1 < KT) {
            store(buf ^ 1);
            __syncthreads();
        }
    }

    // epilogue: relu + store
#pragma unroll
    for (int mi = 0; mi < 2; mi++) {
        int row0 = m0 + wm * 32 + mi * 16 + (lane >> 2);
#pragma unroll
        for (int ni = 0; ni < 8; ni++) {
            int col = wn * 64 + ni * 8 + (lane & 3) * 2;
            if (row0 < N_NODES) {
                float2 v = make_float2(fmaxf(acc[mi][ni][0], 0.f),
                                       fmaxf(acc[mi][ni][1], 0.f));
                *(float2*)&g_h[(size_t)row0 * D_IN + col] = v;
            }
            if (row0 + 8 < N_NODES) {
                float2 v = make_float2(fmaxf(acc[mi][ni][2], 0.f),
                                       fmaxf(acc[mi][ni][3], 0.f));
                *(float2*)&g_h[(size_t)(row0 + 8) * D_IN + col] = v;
            }
        }
    }
}

// ---------------- small dense linears ----------------------------------------
// fused: Y = X @ W ; Acc = Y * dinv[row]^2   (self-loop init for aggregation)
template <int IN, int OUT>
__global__ void k_linear_agg(const float* __restrict__ X,
                             const float* __restrict__ W,
                             float* __restrict__ Y,
                             float* __restrict__ Acc)
{
    int col = threadIdx.x;
    int row = blockIdx.x * blockDim.y + threadIdx.y;
    if (row >= N_NODES) return;
    const float* xr = X + (size_t)row * IN;
    float acc = 0.0f;
#pragma unroll 8
    for (int k = 0; k < IN; k++)
        acc = fmaf(xr[k], W[k * OUT + col], acc);
    float di = g_dinv[row];
    Y[(size_t)row * OUT + col]   = acc;
    Acc[(size_t)row * OUT + col] = acc * di * di;
}

template <int IN, int OUT>
__global__ void k_linear(const float* __restrict__ X,
                         const float* __restrict__ W,
                         float* __restrict__ Y)
{
    int col = threadIdx.x;
    int row = blockIdx.x * blockDim.y + threadIdx.y;
    if (row >= N_NODES) return;
    const float* xr = X + (size_t)row * IN;
    float acc = 0.0f;
#pragma unroll 8
    for (int k = 0; k < IN; k++)
        acc = fmaf(xr[k], W[k * OUT + col], acc);
    Y[(size_t)row * OUT + col] = acc;
}

// ---------------- GCN aggregation --------------------------------------------
template <int F>
__global__ void k_agg_edges(const float* __restrict__ X,
                            float* __restrict__ Acc)
{
    int f = threadIdx.x;
    int e = blockIdx.x * blockDim.y + threadIdx.y;
    if (e >= N_EDGES) return;
    int s = g_src[e];
    int d = g_dst[e];
    float norm = g_dinv[s] * g_dinv[d];
    atomicAdd(&Acc[(size_t)d * F + f], X[(size_t)s * F + f] * norm);
}

template <int F>
__global__ void k_agg_finish(const float* __restrict__ Acc,
                             const float* __restrict__ bias,
                             float* __restrict__ Y)
{
    int f = threadIdx.x;
    int i = blockIdx.x * blockDim.y + threadIdx.y;
    if (i >= N_NODES) return;
    Y[(size_t)i * F + f] = fmaxf(Acc[(size_t)i * F + f] + bias[f], 0.0f);
}

// ---------------- launch -----------------------------------------------------
extern "C" void kernel_launch(void* const* d_in, const int* in_sizes, int n_in,
                              void* d_out, int out_size)
{
    const float* x    = (const float*)d_in[0];
    const void*  ei   = d_in[1];
    const float* emb  = (const float*)d_in[2];
    const float* W1   = (const float*)d_in[3];
    const float* b1   = (const float*)d_in[4];
    const float* W2   = (const float*)d_in[5];
    const float* b2   = (const float*)d_in[6];
    const float* decW = (const float*)d_in[7];
    float*       out  = (float*)d_out;

    float *gh, *gt1, *ga1, *gt2, *ga2;
    int* gdeg;
    cudaGetSymbolAddress((void**)&gh,  g_h);
    cudaGetSymbolAddress((void**)&gt1, g_t1);
    cudaGetSymbolAddress((void**)&ga1, g_a1);
    cudaGetSymbolAddress((void**)&gt2, g_t2);
    cudaGetSymbolAddress((void**)&ga2, g_a2);
    cudaGetSymbolAddress((void**)&gdeg, g_deg);

    cudaFuncSetAttribute(k_gemm1_f16, cudaFuncAttributeMaxDynamicSharedMemorySize, GEMM_SMEM);

    // graph structure
    cudaMemsetAsync(gdeg, 0, N_NODES * sizeof(int));
    k_detect<<<1, 32>>>(ei);
    k_decode_deg<<<(N_EDGES + 255) / 256, 256>>>(ei);
    k_dinv<<<(N_NODES + 255) / 256, 256>>>();

    // h = relu(x @ emb) — fp16 tensor cores, one wave (79 CTAs)
    k_gemm1_f16<<<(N_NODES + 127) / 128, 512, GEMM_SMEM>>>(x, emb);

    // layer 1
    {
        dim3 blk(D_H1, 256 / D_H1);
        k_linear_agg<D_IN, D_H1><<<(N_NODES + blk.y - 1) / blk.y, blk>>>(gh, W1, gt1, ga1);
        k_agg_edges<D_H1><<<(N_EDGES + blk.y - 1) / blk.y, blk>>>(gt1, ga1);
        k_agg_finish<D_H1><<<(N_NODES + blk.y - 1) / blk.y, blk>>>(ga1, b1, gt1);
    }

    // layer 2
    {
        dim3 blk(D_H2, 256 / D_H2);
        k_linear_agg<D_H1, D_H2><<<(N_NODES + blk.y - 1) / blk.y, blk>>>(gt1, W2, gt2, ga2);
        k_agg_edges<D_H2><<<(N_EDGES + blk.y - 1) / blk.y, blk>>>(gt2, ga2);
        k_agg_finish<D_H2><<<(N_NODES + blk.y - 1) / blk.y, blk>>>(ga2, b2, gt2);
    }

    // decoder
    {
        dim3 blk(D_OUT, 256 / D_OUT);
        k_linear<D_H2, D_OUT><<<(N_NODES + blk.y - 1) / blk.y, blk>>>(gt2, decW, out);
    }
}

// round 8
// speedup vs baseline: 4.0837x; 1.1598x over previous
#include <cuda_runtime.h>
#include <cuda_fp16.h>
#include <math.h>
#include <stdint.h>

#define N_NODES 10000
#define N_EDGES 640000
#define D_IN    256
#define D_H1    64
#define D_H2    32
#define D_OUT   16

#define K_PAD   10016            // 313 * 32
#define M_PAD   10112            // 79 * 128
#define KT      313

// ---------------- scratch (device globals; no allocation allowed) ------------
__device__ __half g_Ah[(size_t)M_PAD * K_PAD];   // fp16 x, padded
__device__ __half g_Bh[(size_t)K_PAD * D_IN];    // fp16 emb, K-padded
__device__ float g_h [N_NODES * D_IN];
__device__ float g_t1[N_NODES * D_H1];
__device__ float g_a1[N_NODES * D_H1];
__device__ float g_t2[N_NODES * D_H2];
__device__ float g_a2[N_NODES * D_H2];
__device__ int   g_src[N_EDGES];
__device__ int   g_dst[N_EDGES];
__device__ int   g_csr_src[N_EDGES];
__device__ float g_csr_w[N_EDGES];
__device__ int   g_rowptr[N_NODES + 1];
__device__ int   g_cursor[N_NODES];
__device__ int   g_deg [N_NODES];
__device__ float g_dinv[N_NODES];
__device__ int   g_is64;

// ---------------- edge index dtype detection + decode (+deg count) -----------
__global__ void k_detect(const void* __restrict__ ei) {
    if (threadIdx.x == 0 && blockIdx.x == 0) {
        const long long* p = (const long long*)ei;
        int ok = 1;
        for (int i = 0; i < 16; i++) {
            long long v = p[i];
            if (v < 0 || v >= N_NODES) ok = 0;
        }
        g_is64 = ok;
    }
}

__global__ void k_decode_deg(const void* __restrict__ ei) {
    int e = blockIdx.x * blockDim.x + threadIdx.x;
    if (e >= N_EDGES) return;
    int s, d;
    if (g_is64) {
        const long long* p = (const long long*)ei;
        s = (int)p[e]; d = (int)p[N_EDGES + e];
    } else {
        const int* p = (const int*)ei;
        s = p[e]; d = p[N_EDGES + e];
    }
    g_src[e] = s;
    g_dst[e] = d;
    atomicAdd(&g_deg[d], 1);
}

__global__ void k_dinv() {
    int i = blockIdx.x * blockDim.x + threadIdx.x;
    if (i < N_NODES) g_dinv[i] = rsqrtf((float)(g_deg[i] + 1));
}

// ---------------- CSR build ---------------------------------------------------
__global__ __launch_bounds__(1024) void k_scan() {     // single block
    __shared__ int sm1[1024];
    const int t = threadIdx.x;
    const int base = t * 10;
    int loc[10];
    int s = 0;
#pragma unroll
    for (int j = 0; j < 10; j++) {
        int i = base + j;
        int v = (i < N_NODES) ? g_deg[i] : 0;
        loc[j] = s;
        s += v;
    }
    sm1[t] = s;
    __syncthreads();
    for (int off = 1; off < 1024; off <<= 1) {
        int v = (t >= off) ? sm1[t - off] : 0;
        __syncthreads();
        sm1[t] += v;
        __syncthreads();
    }
    int pre = (t > 0) ? sm1[t - 1] : 0;
#pragma unroll
    for (int j = 0; j < 10; j++) {
        int i = base + j;
        if (i < N_NODES) {
            g_rowptr[i] = pre + loc[j];
            g_cursor[i] = pre + loc[j];
        }
    }
    if (t == 1023) g_rowptr[N_NODES] = sm1[1023];
}

__global__ void k_fill_csr() {
    int e = blockIdx.x * blockDim.x + threadIdx.x;
    if (e >= N_EDGES) return;
    int s = g_src[e], d = g_dst[e];
    int pos = atomicAdd(&g_cursor[d], 1);
    g_csr_src[pos] = s;
    g_csr_w[pos]   = g_dinv[s];
}

// ---------------- fp16 prep ---------------------------------------------------
__global__ void k_prep_a(const float* __restrict__ x) {
    int c8  = blockIdx.x * blockDim.x + threadIdx.x;   // 8-half chunk
    int row = blockIdx.y;
    if (c8 >= K_PAD / 8) return;
    __half2 h[4];
    if (row < N_NODES && c8 < N_NODES / 8) {
        const float4* p = (const float4*)&x[(size_t)row * N_NODES + c8 * 8];
        float4 v0 = p[0], v1 = p[1];
        h[0] = __floats2half2_rn(v0.x, v0.y);
        h[1] = __floats2half2_rn(v0.z, v0.w);
        h[2] = __floats2half2_rn(v1.x, v1.y);
        h[3] = __floats2half2_rn(v1.z, v1.w);
    } else {
        h[0] = h[1] = h[2] = h[3] = __floats2half2_rn(0.f, 0.f);
    }
    *(uint4*)&g_Ah[(size_t)row * K_PAD + c8 * 8] = *(uint4*)h;
}

__global__ void k_prep_b(const float* __restrict__ emb) {
    int chunk = blockIdx.x * blockDim.x + threadIdx.x; // 8-half chunk
    if (chunk >= K_PAD * D_IN / 8) return;
    int row = chunk >> 5;        // 32 chunks per 256-wide row
    int c   = chunk & 31;
    __half2 h[4];
    if (row < N_NODES) {
        const float4* p = (const float4*)&emb[(size_t)row * D_IN + c * 8];
        float4 v0 = p[0], v1 = p[1];
        h[0] = __floats2half2_rn(v0.x, v0.y);
        h[1] = __floats2half2_rn(v0.z, v0.w);
        h[2] = __floats2half2_rn(v1.x, v1.y);
        h[3] = __floats2half2_rn(v1.z, v1.w);
    } else {
        h[0] = h[1] = h[2] = h[3] = __floats2half2_rn(0.f, 0.f);
    }
    *(uint4*)&g_Bh[(size_t)row * D_IN + c * 8] = *(uint4*)h;
}

// ---------------- GEMM1 (fp16 HMMA + cp.async pipeline) -----------------------
// BM=128 BN=256 BK=32, 512 threads (16 warps = 4M x 4N), 4 smem stages.
#define LDA_H 40
#define LDB_H 264
#define AS_STG (128 * LDA_H)          // halfs
#define BS_STG (32 * LDB_H)
#define BS_OFF (4 * AS_STG)
#define GEMM_SMEM ((4 * AS_STG + 4 * BS_STG) * 2)   // 108544 B

__device__ __forceinline__ uint32_t smem_u32(const void* p) {
    uint32_t a;
    asm("{ .reg .u64 t; cvta.to.shared.u64 t, %1; cvt.u32.u64 %0, t; }"
        : "=r"(a) : "l"(p));
    return a;
}
__device__ __forceinline__ void cp16(uint32_t dst, const void* src) {
    asm volatile("cp.async.cg.shared.global [%0], [%1], 16;" :: "r"(dst), "l"(src) : "memory");
}
__device__ __forceinline__ void cp_commit() {
    asm volatile("cp.async.commit_group;" ::: "memory");
}
template <int NW>
__device__ __forceinline__ void cp_wait() {
    asm volatile("cp.async.wait_group %0;" :: "n"(NW) : "memory");
}
__device__ __forceinline__ void ldsm4(uint32_t* r, uint32_t addr) {
    asm volatile("ldmatrix.sync.aligned.m8n8.x4.shared.b16 {%0,%1,%2,%3}, [%4];"
                 : "=r"(r[0]), "=r"(r[1]), "=r"(r[2]), "=r"(r[3]) : "r"(addr));
}
__device__ __forceinline__ void ldsm4t(uint32_t* r, uint32_t addr) {
    asm volatile("ldmatrix.sync.aligned.m8n8.x4.trans.shared.b16 {%0,%1,%2,%3}, [%4];"
                 : "=r"(r[0]), "=r"(r[1]), "=r"(r[2]), "=r"(r[3]) : "r"(addr));
}
__device__ __forceinline__ void mma_f16(float* c, const uint32_t* a, uint32_t b0, uint32_t b1) {
    asm volatile(
        "mma.sync.aligned.m16n8k16.row.col.f32.f16.f16.f32 "
        "{%0,%1,%2,%3}, {%4,%5,%6,%7}, {%8,%9}, {%0,%1,%2,%3};"
        : "+f"(c[0]), "+f"(c[1]), "+f"(c[2]), "+f"(c[3])
        : "r"(a[0]), "r"(a[1]), "r"(a[2]), "r"(a[3]), "r"(b0), "r"(b1));
}

__global__ __launch_bounds__(512, 1)
void k_gemm1_f16()
{
    extern __shared__ __half sm[];
    const int tid  = threadIdx.x;
    const int lane = tid & 31;
    const int wid  = tid >> 5;
    const int wm   = wid & 3;
    const int wn   = wid >> 2;
    const int m0   = blockIdx.x * 128;
    const uint32_t sbase = smem_u32(sm);

    float acc[2][8][4];
#pragma unroll
    for (int mi = 0; mi < 2; mi++)
#pragma unroll
        for (int ni = 0; ni < 8; ni++)
#pragma unroll
            for (int r = 0; r < 4; r++) acc[mi][ni][r] = 0.0f;

    // fill stage: A 512 chunks (1/thread), B 1024 chunks (2/thread)
    const int a_row = tid >> 2, a_c = tid & 3;
    const __half* a_src0 = &g_Ah[(size_t)(m0 + a_row) * K_PAD + a_c * 8];

    auto fill = [&](int slot, int it) {
        const int k0 = it * 32;
        cp16(sbase + (slot * AS_STG + a_row * LDA_H) * 2 + a_c * 16, a_src0 + k0);
#pragma unroll
        for (int i = 0; i < 2; i++) {
            int ch = tid + i * 512;
            int row = ch >> 5, c = ch & 31;
            cp16(sbase + (BS_OFF + slot * BS_STG + row * LDB_H) * 2 + c * 16,
                 &g_Bh[(size_t)(k0 + row) * D_IN + c * 8]);
        }
        cp_commit();
    };

    const uint32_t a_lane_off = ((lane & 15) * LDA_H + (lane >> 4) * 8) * 2;
    const uint32_t b_lane_off = ((lane & 15) * LDB_H + (lane >> 4) * 8) * 2;

    auto compute = [&](int slot) {
        const uint32_t abase = sbase + slot * (AS_STG * 2);
        const uint32_t bbase = sbase + (BS_OFF + slot * BS_STG) * 2;
#pragma unroll
        for (int ks = 0; ks < 2; ks++) {
            uint32_t a[2][4], b[4][4];
#pragma unroll
            for (int mi = 0; mi < 2; mi++)
                ldsm4(a[mi], abase + a_lane_off +
                             ((wm * 32 + mi * 16) * LDA_H + ks * 16) * 2);
#pragma unroll
            for (int g = 0; g < 4; g++)
                ldsm4t(b[g], bbase + b_lane_off +
                             (ks * 16 * LDB_H + wn * 64 + g * 16) * 2);
#pragma unroll
            for (int mi = 0; mi < 2; mi++)
#pragma unroll
                for (int g = 0; g < 4; g++) {
                    mma_f16(acc[mi][g * 2 + 0], a[mi], b[g][0], b[g][1]);
                    mma_f16(acc[mi][g * 2 + 1], a[mi], b[g][2], b[g][3]);
                }
        }
    };

    // prologue: stages 0..2
    fill(0, 0);
    fill(1, 1);
    fill(2, 2);

    for (int it = 0; it < KT; ++it) {
        cp_wait<2>();
        __syncthreads();
        if (it + 3 < KT) fill((it + 3) & 3, it + 3);
        compute(it & 3);
    }

    // epilogue: relu + store
#pragma unroll
    for (int mi = 0; mi < 2; mi++) {
        int row0 = m0 + wm * 32 + mi * 16 + (lane >> 2);
#pragma unroll
        for (int ni = 0; ni < 8; ni++) {
            int col = wn * 64 + ni * 8 + (lane & 3) * 2;
            if (row0 < N_NODES) {
                float2 v = make_float2(fmaxf(acc[mi][ni][0], 0.f),
                                       fmaxf(acc[mi][ni][1], 0.f));
                *(float2*)&g_h[(size_t)row0 * D_IN + col] = v;
            }
            if (row0 + 8 < N_NODES) {
                float2 v = make_float2(fmaxf(acc[mi][ni][2], 0.f),
                                       fmaxf(acc[mi][ni][3], 0.f));
                *(float2*)&g_h[(size_t)(row0 + 8) * D_IN + col] = v;
            }
        }
    }
}

// ---------------- small dense linears: Y = X @ W -----------------------------
template <int IN, int OUT>
__global__ void k_linear(const float* __restrict__ X,
                         const float* __restrict__ W,
                         float* __restrict__ Y)
{
    int col = threadIdx.x;
    int row = blockIdx.x * blockDim.y + threadIdx.y;
    if (row >= N_NODES) return;
    const float* xr = X + (size_t)row * IN;
    float acc = 0.0f;
#pragma unroll 8
    for (int k = 0; k < IN; k++)
        acc = fmaf(xr[k], W[k * OUT + col], acc);
    Y[(size_t)row * OUT + col] = acc;
}

// ---------------- CSR gather aggregation + bias + relu ------------------------
// Y[i] = relu(dinv[i] * (X[i]*dinv[i] + sum_nbr X[s]*dinv[s]) + b)
template <int F>
__global__ void k_gather(const float* __restrict__ X,
                         const float* __restrict__ bias,
                         float* __restrict__ Y)
{
    int f = threadIdx.x;
    int i = blockIdx.x * blockDim.y + threadIdx.y;
    if (i >= N_NODES) return;
    int beg = g_rowptr[i], end = g_rowptr[i + 1];
    float di  = g_dinv[i];
    float acc = X[(size_t)i * F + f] * di;
    int j = beg;
    for (; j + 4 <= end; j += 4) {
        int   s0 = g_csr_src[j],     s1 = g_csr_src[j + 1];
        int   s2 = g_csr_src[j + 2], s3 = g_csr_src[j + 3];
        float w0 = g_csr_w[j],       w1 = g_csr_w[j + 1];
        float w2 = g_csr_w[j + 2],   w3 = g_csr_w[j + 3];
        acc = fmaf(X[(size_t)s0 * F + f], w0, acc);
        acc = fmaf(X[(size_t)s1 * F + f], w1, acc);
        acc = fmaf(X[(size_t)s2 * F + f], w2, acc);
        acc = fmaf(X[(size_t)s3 * F + f], w3, acc);
    }
    for (; j < end; j++)
        acc = fmaf(X[(size_t)g_csr_src[j] * F + f], g_csr_w[j], acc);
    Y[(size_t)i * F + f] = fmaxf(fmaf(acc, di, bias[f]), 0.0f);
}

// ---------------- launch -----------------------------------------------------
extern "C" void kernel_launch(void* const* d_in, const int* in_sizes, int n_in,
                              void* d_out, int out_size)
{
    const float* x    = (const float*)d_in[0];
    const void*  ei   = d_in[1];
    const float* emb  = (const float*)d_in[2];
    const float* W1   = (const float*)d_in[3];
    const float* b1   = (const float*)d_in[4];
    const float* W2   = (const float*)d_in[5];
    const float* b2   = (const float*)d_in[6];
    const float* decW = (const float*)d_in[7];
    float*       out  = (float*)d_out;

    float *gh, *gt1, *ga1, *gt2, *ga2;
    int* gdeg;
    cudaGetSymbolAddress((void**)&gh,  g_h);
    cudaGetSymbolAddress((void**)&gt1, g_t1);
    cudaGetSymbolAddress((void**)&ga1, g_a1);
    cudaGetSymbolAddress((void**)&gt2, g_t2);
    cudaGetSymbolAddress((void**)&ga2, g_a2);
    cudaGetSymbolAddress((void**)&gdeg, g_deg);

    cudaFuncSetAttribute(k_gemm1_f16, cudaFuncAttributeMaxDynamicSharedMemorySize, GEMM_SMEM);

    // graph structure: deg -> dinv -> CSR
    cudaMemsetAsync(gdeg, 0, N_NODES * sizeof(int));
    k_detect<<<1, 32>>>(ei);
    k_decode_deg<<<(N_EDGES + 255) / 256, 256>>>(ei);
    k_dinv<<<(N_NODES + 255) / 256, 256>>>();
    k_scan<<<1, 1024>>>();
    k_fill_csr<<<(N_EDGES + 255) / 256, 256>>>();

    // fp16 prep for GEMM1
    {
        dim3 grid((K_PAD / 8 + 255) / 256, M_PAD);
        k_prep_a<<<grid, 256>>>(x);
        k_prep_b<<<(K_PAD * D_IN / 8 + 255) / 256, 256>>>(emb);
    }

    // h = relu(x @ emb)
    k_gemm1_f16<<<M_PAD / 128, 512, GEMM_SMEM>>>();

    // layer 1: t1 = h @ W1 ; CSR-gather+bias+relu -> a1
    {
        dim3 blk(D_H1, 256 / D_H1);
        k_linear<D_IN, D_H1><<<(N_NODES + blk.y - 1) / blk.y, blk>>>(gh, W1, gt1);
        dim3 gblk(D_H1, 512 / D_H1);
        k_gather<D_H1><<<(N_NODES + gblk.y - 1) / gblk.y, gblk>>>(gt1, b1, ga1);
    }

    // layer 2: t2 = a1 @ W2 ; CSR-gather+bias+relu -> a2
    {
        dim3 blk(D_H2, 256 / D_H2);
        k_linear<D_H1, D_H2><<<(N_NODES + blk.y - 1) / blk.y, blk>>>(ga1, W2, gt2);
        dim3 gblk(D_H2, 512 / D_H2);
        k_gather<D_H2><<<(N_NODES + gblk.y - 1) / gblk.y, gblk>>>(gt2, b2, ga2);
    }

    // decoder: out = a2 @ dec_W
    {
        dim3 blk(D_OUT, 256 / D_OUT);
        k_linear<D_H2, D_OUT><<<(N_NODES + blk.y - 1) / blk.y, blk>>>(ga2, decW, out);
    }
}

// round 9
// speedup vs baseline: 4.1000x; 1.0040x over previous
#include <cuda_runtime.h>
#include <cuda_fp16.h>
#include <math.h>
#include <stdint.h>

#define N_NODES 10000
#define N_EDGES 640000
#define D_IN    256
#define D_H1    64
#define D_H2    32
#define D_OUT   16

#define K_PAD   10016            // 313 * 32
#define M_PAD   10112            // 79 * 128
#define KT      313

// ---------------- scratch (device globals; no allocation allowed) ------------
__device__ __half g_Ah[(size_t)M_PAD * K_PAD];   // fp16 x, padded
__device__ __half g_Bh[(size_t)K_PAD * D_IN];    // fp16 emb, K-padded
__device__ float g_h [N_NODES * D_IN];
__device__ float g_t1[N_NODES * D_H1];
__device__ float g_a1[N_NODES * D_H1];
__device__ float g_t2[N_NODES * D_H2];
__device__ float g_a2[N_NODES * D_H2];
__device__ int   g_src[N_EDGES];
__device__ int   g_dst[N_EDGES];
__device__ int   g_csr_src[N_EDGES];
__device__ float g_csr_w[N_EDGES];
__device__ int   g_rowptr[N_NODES + 1];
__device__ int   g_cursor[N_NODES];
__device__ int   g_deg [N_NODES];
__device__ float g_dinv[N_NODES];
__device__ int   g_is64;

// ---------------- edge index dtype detection + decode (+deg count) -----------
__global__ void k_detect(const void* __restrict__ ei) {
    if (threadIdx.x == 0 && blockIdx.x == 0) {
        const long long* p = (const long long*)ei;
        int ok = 1;
        for (int i = 0; i < 16; i++) {
            long long v = p[i];
            if (v < 0 || v >= N_NODES) ok = 0;
        }
        g_is64 = ok;
    }
}

__global__ void k_decode_deg(const void* __restrict__ ei) {
    int e = blockIdx.x * blockDim.x + threadIdx.x;
    if (e >= N_EDGES) return;
    int s, d;
    if (g_is64) {
        const long long* p = (const long long*)ei;
        s = (int)p[e]; d = (int)p[N_EDGES + e];
    } else {
        const int* p = (const int*)ei;
        s = p[e]; d = p[N_EDGES + e];
    }
    g_src[e] = s;
    g_dst[e] = d;
    atomicAdd(&g_deg[d], 1);
}

__global__ void k_dinv() {
    int i = blockIdx.x * blockDim.x + threadIdx.x;
    if (i < N_NODES) g_dinv[i] = rsqrtf((float)(g_deg[i] + 1));
}

// ---------------- CSR build ---------------------------------------------------
__global__ __launch_bounds__(1024) void k_scan() {     // single block
    __shared__ int sm1[1024];
    const int t = threadIdx.x;
    const int base = t * 10;
    int loc[10];
    int s = 0;
#pragma unroll
    for (int j = 0; j < 10; j++) {
        int i = base + j;
        int v = (i < N_NODES) ? g_deg[i] : 0;
        loc[j] = s;
        s += v;
    }
    sm1[t] = s;
    __syncthreads();
    for (int off = 1; off < 1024; off <<= 1) {
        int v = (t >= off) ? sm1[t - off] : 0;
        __syncthreads();
        sm1[t] += v;
        __syncthreads();
    }
    int pre = (t > 0) ? sm1[t - 1] : 0;
#pragma unroll
    for (int j = 0; j < 10; j++) {
        int i = base + j;
        if (i < N_NODES) {
            g_rowptr[i] = pre + loc[j];
            g_cursor[i] = pre + loc[j];
        }
    }
    if (t == 1023) g_rowptr[N_NODES] = sm1[1023];
}

__global__ void k_fill_csr() {
    int e = blockIdx.x * blockDim.x + threadIdx.x;
    if (e >= N_EDGES) return;
    int s = g_src[e], d = g_dst[e];
    int pos = atomicAdd(&g_cursor[d], 1);
    g_csr_src[pos] = s;
    g_csr_w[pos]   = g_dinv[s];
}

// ---------------- fp16 prep ---------------------------------------------------
__global__ void k_prep_a(const float* __restrict__ x) {
    int c8  = blockIdx.x * blockDim.x + threadIdx.x;   // 8-half chunk
    int row = blockIdx.y;
    if (c8 >= K_PAD / 8) return;
    __half2 h[4];
    if (row < N_NODES && c8 < N_NODES / 8) {
        const float4* p = (const float4*)&x[(size_t)row * N_NODES + c8 * 8];
        float4 v0 = p[0], v1 = p[1];
        h[0] = __floats2half2_rn(v0.x, v0.y);
        h[1] = __floats2half2_rn(v0.z, v0.w);
        h[2] = __floats2half2_rn(v1.x, v1.y);
        h[3] = __floats2half2_rn(v1.z, v1.w);
    } else {
        h[0] = h[1] = h[2] = h[3] = __floats2half2_rn(0.f, 0.f);
    }
    *(uint4*)&g_Ah[(size_t)row * K_PAD + c8 * 8] = *(uint4*)h;
}

__global__ void k_prep_b(const float* __restrict__ emb) {
    int chunk = blockIdx.x * blockDim.x + threadIdx.x; // 8-half chunk
    if (chunk >= K_PAD * D_IN / 8) return;
    int row = chunk >> 5;        // 32 chunks per 256-wide row
    int c   = chunk & 31;
    __half2 h[4];
    if (row < N_NODES) {
        const float4* p = (const float4*)&emb[(size_t)row * D_IN + c * 8];
        float4 v0 = p[0], v1 = p[1];
        h[0] = __floats2half2_rn(v0.x, v0.y);
        h[1] = __floats2half2_rn(v0.z, v0.w);
        h[2] = __floats2half2_rn(v1.x, v1.y);
        h[3] = __floats2half2_rn(v1.z, v1.w);
    } else {
        h[0] = h[1] = h[2] = h[3] = __floats2half2_rn(0.f, 0.f);
    }
    *(uint4*)&g_Bh[(size_t)row * D_IN + c * 8] = *(uint4*)h;
}

// ---------------- GEMM1 (fp16 HMMA + cp.async pipeline) -----------------------
// BM=128 BN=128 BK=32, 256 threads (8 warps = 4M x 2N), 4 smem stages.
// grid = (79, 2) = 158 CTAs -> full chip (was 79 = half idle).
#define LDA_H 40
#define LDB_H 136
#define AS_STG (128 * LDA_H)          // 5120 halfs
#define BS_STG (32 * LDB_H)           // 4352 halfs
#define BS_OFF (4 * AS_STG)
#define GEMM_SMEM ((4 * AS_STG + 4 * BS_STG) * 2)   // 75776 B

__device__ __forceinline__ uint32_t smem_u32(const void* p) {
    uint32_t a;
    asm("{ .reg .u64 t; cvta.to.shared.u64 t, %1; cvt.u32.u64 %0, t; }"
        : "=r"(a) : "l"(p));
    return a;
}
__device__ __forceinline__ void cp16(uint32_t dst, const void* src) {
    asm volatile("cp.async.cg.shared.global [%0], [%1], 16;" :: "r"(dst), "l"(src) : "memory");
}
__device__ __forceinline__ void cp_commit() {
    asm volatile("cp.async.commit_group;" ::: "memory");
}
template <int NW>
__device__ __forceinline__ void cp_wait() {
    asm volatile("cp.async.wait_group %0;" :: "n"(NW) : "memory");
}
__device__ __forceinline__ void ldsm4(uint32_t* r, uint32_t addr) {
    asm volatile("ldmatrix.sync.aligned.m8n8.x4.shared.b16 {%0,%1,%2,%3}, [%4];"
                 : "=r"(r[0]), "=r"(r[1]), "=r"(r[2]), "=r"(r[3]) : "r"(addr));
}
__device__ __forceinline__ void ldsm4t(uint32_t* r, uint32_t addr) {
    asm volatile("ldmatrix.sync.aligned.m8n8.x4.trans.shared.b16 {%0,%1,%2,%3}, [%4];"
                 : "=r"(r[0]), "=r"(r[1]), "=r"(r[2]), "=r"(r[3]) : "r"(addr));
}
__device__ __forceinline__ void mma_f16(float* c, const uint32_t* a, uint32_t b0, uint32_t b1) {
    asm volatile(
        "mma.sync.aligned.m16n8k16.row.col.f32.f16.f16.f32 "
        "{%0,%1,%2,%3}, {%4,%5,%6,%7}, {%8,%9}, {%0,%1,%2,%3};"
        : "+f"(c[0]), "+f"(c[1]), "+f"(c[2]), "+f"(c[3])
        : "r"(a[0]), "r"(a[1]), "r"(a[2]), "r"(a[3]), "r"(b0), "r"(b1));
}

__global__ __launch_bounds__(256, 2)
void k_gemm1_f16()
{
    extern __shared__ __half sm[];
    const int tid  = threadIdx.x;
    const int lane = tid & 31;
    const int wid  = tid >> 5;
    const int wm   = wid & 3;        // 0..3 (M)
    const int wn   = wid >> 2;       // 0..1 (N)
    const int m0   = blockIdx.x * 128;
    const int n0   = blockIdx.y * 128;
    const uint32_t sbase = smem_u32(sm);

    float acc[2][8][4];
#pragma unroll
    for (int mi = 0; mi < 2; mi++)
#pragma unroll
        for (int ni = 0; ni < 8; ni++)
#pragma unroll
            for (int r = 0; r < 4; r++) acc[mi][ni][r] = 0.0f;

    // fill: A 512 chunks (2/thread), B 512 chunks (2/thread)
    auto fill = [&](int slot, int it) {
        const int k0 = it * 32;
#pragma unroll
        for (int i = 0; i < 2; i++) {
            int ch = tid + i * 256;
            int row = ch >> 2, c = ch & 3;           // 4 chunks per 32-half row
            cp16(sbase + (slot * AS_STG + row * LDA_H) * 2 + c * 16,
                 &g_Ah[(size_t)(m0 + row) * K_PAD + k0 + c * 8]);
        }
#pragma unroll
        for (int i = 0; i < 2; i++) {
            int ch = tid + i * 256;
            int row = ch >> 4, c = ch & 15;          // 16 chunks per 128-half row
            cp16(sbase + (BS_OFF + slot * BS_STG + row * LDB_H) * 2 + c * 16,
                 &g_Bh[(size_t)(k0 + row) * D_IN + n0 + c * 8]);
        }
        cp_commit();
    };

    const uint32_t a_lane_off = ((lane & 15) * LDA_H + (lane >> 4) * 8) * 2;
    const uint32_t b_lane_off = ((lane & 15) * LDB_H + (lane >> 4) * 8) * 2;

    auto compute = [&](int slot) {
        const uint32_t abase = sbase + slot * (AS_STG * 2);
        const uint32_t bbase = sbase + (BS_OFF + slot * BS_STG) * 2;
#pragma unroll
        for (int ks = 0; ks < 2; ks++) {
            uint32_t a[2][4], b[4][4];
#pragma unroll
            for (int mi = 0; mi < 2; mi++)
                ldsm4(a[mi], abase + a_lane_off +
                             ((wm * 32 + mi * 16) * LDA_H + ks * 16) * 2);
#pragma unroll
            for (int g = 0; g < 4; g++)
                ldsm4t(b[g], bbase + b_lane_off +
                             (ks * 16 * LDB_H + wn * 64 + g * 16) * 2);
#pragma unroll
            for (int mi = 0; mi < 2; mi++)
#pragma unroll
                for (int g = 0; g < 4; g++) {
                    mma_f16(acc[mi][g * 2 + 0], a[mi], b[g][0], b[g][1]);
                    mma_f16(acc[mi][g * 2 + 1], a[mi], b[g][2], b[g][3]);
                }
        }
    };

    // prologue: stages 0..2
    fill(0, 0);
    fill(1, 1);
    fill(2, 2);

    for (int it = 0; it < KT; ++it) {
        cp_wait<2>();
        __syncthreads();
        if (it + 3 < KT) fill((it + 3) & 3, it + 3);
        compute(it & 3);
    }

    // epilogue: relu + store
#pragma unroll
    for (int mi = 0; mi < 2; mi++) {
        int row0 = m0 + wm * 32 + mi * 16 + (lane >> 2);
#pragma unroll
        for (int ni = 0; ni < 8; ni++) {
            int col = n0 + wn * 64 + ni * 8 + (lane & 3) * 2;
            if (row0 < N_NODES) {
                float2 v = make_float2(fmaxf(acc[mi][ni][0], 0.f),
                                       fmaxf(acc[mi][ni][1], 0.f));
                *(float2*)&g_h[(size_t)row0 * D_IN + col] = v;
            }
            if (row0 + 8 < N_NODES) {
                float2 v = make_float2(fmaxf(acc[mi][ni][2], 0.f),
                                       fmaxf(acc[mi][ni][3], 0.f));
                *(float2*)&g_h[(size_t)(row0 + 8) * D_IN + col] = v;
            }
        }
    }
}

// ---------------- small dense linears: Y = X @ W -----------------------------
template <int IN, int OUT>
__global__ void k_linear(const float* __restrict__ X,
                         const float* __restrict__ W,
                         float* __restrict__ Y)
{
    int col = threadIdx.x;
    int row = blockIdx.x * blockDim.y + threadIdx.y;
    if (row >= N_NODES) return;
    const float* xr = X + (size_t)row * IN;
    float acc = 0.0f;
#pragma unroll 8
    for (int k = 0; k < IN; k++)
        acc = fmaf(xr[k], W[k * OUT + col], acc);
    Y[(size_t)row * OUT + col] = acc;
}

// ---------------- CSR gather aggregation + bias + relu ------------------------
template <int F>
__global__ void k_gather(const float* __restrict__ X,
                         const float* __restrict__ bias,
                         float* __restrict__ Y)
{
    int f = threadIdx.x;
    int i = blockIdx.x * blockDim.y + threadIdx.y;
    if (i >= N_NODES) return;
    int beg = g_rowptr[i], end = g_rowptr[i + 1];
    float di  = g_dinv[i];
    float acc = X[(size_t)i * F + f] * di;
    int j = beg;
    for (; j + 4 <= end; j += 4) {
        int   s0 = g_csr_src[j],     s1 = g_csr_src[j + 1];
        int   s2 = g_csr_src[j + 2], s3 = g_csr_src[j + 3];
        float w0 = g_csr_w[j],       w1 = g_csr_w[j + 1];
        float w2 = g_csr_w[j + 2],   w3 = g_csr_w[j + 3];
        acc = fmaf(X[(size_t)s0 * F + f], w0, acc);
        acc = fmaf(X[(size_t)s1 * F + f], w1, acc);
        acc = fmaf(X[(size_t)s2 * F + f], w2, acc);
        acc = fmaf(X[(size_t)s3 * F + f], w3, acc);
    }
    for (; j < end; j++)
        acc = fmaf(X[(size_t)g_csr_src[j] * F + f], g_csr_w[j], acc);
    Y[(size_t)i * F + f] = fmaxf(fmaf(acc, di, bias[f]), 0.0f);
}

// ---------------- launch -----------------------------------------------------
extern "C" void kernel_launch(void* const* d_in, const int* in_sizes, int n_in,
                              void* d_out, int out_size)
{
    const float* x    = (const float*)d_in[0];
    const void*  ei   = d_in[1];
    const float* emb  = (const float*)d_in[2];
    const float* W1   = (const float*)d_in[3];
    const float* b1   = (const float*)d_in[4];
    const float* W2   = (const float*)d_in[5];
    const float* b2   = (const float*)d_in[6];
    const float* decW = (const float*)d_in[7];
    float*       out  = (float*)d_out;

    float *gh, *gt1, *ga1, *gt2, *ga2;
    int* gdeg;
    cudaGetSymbolAddress((void**)&gh,  g_h);
    cudaGetSymbolAddress((void**)&gt1, g_t1);
    cudaGetSymbolAddress((void**)&ga1, g_a1);
    cudaGetSymbolAddress((void**)&gt2, g_t2);
    cudaGetSymbolAddress((void**)&ga2, g_a2);
    cudaGetSymbolAddress((void**)&gdeg, g_deg);

    cudaFuncSetAttribute(k_gemm1_f16, cudaFuncAttributeMaxDynamicSharedMemorySize, GEMM_SMEM);

    // graph structure: deg -> dinv -> CSR
    cudaMemsetAsync(gdeg, 0, N_NODES * sizeof(int));
    k_detect<<<1, 32>>>(ei);
    k_decode_deg<<<(N_EDGES + 255) / 256, 256>>>(ei);
    k_dinv<<<(N_NODES + 255) / 256, 256>>>();
    k_scan<<<1, 1024>>>();
    k_fill_csr<<<(N_EDGES + 255) / 256, 256>>>();

    // fp16 prep for GEMM1
    {
        dim3 grid((K_PAD / 8 + 255) / 256, M_PAD);
        k_prep_a<<<grid, 256>>>(x);
        k_prep_b<<<(K_PAD * D_IN / 8 + 255) / 256, 256>>>(emb);
    }

    // h = relu(x @ emb)  — 158 CTAs (full chip)
    k_gemm1_f16<<<dim3(M_PAD / 128, 2), 256, GEMM_SMEM>>>();

    // layer 1: t1 = h @ W1 ; CSR-gather+bias+relu -> a1
    {
        dim3 blk(D_H1, 256 / D_H1);
        k_linear<D_IN, D_H1><<<(N_NODES + blk.y - 1) / blk.y, blk>>>(gh, W1, gt1);
        dim3 gblk(D_H1, 512 / D_H1);
        k_gather<D_H1><<<(N_NODES + gblk.y - 1) / gblk.y, gblk>>>(gt1, b1, ga1);
    }

    // layer 2: t2 = a1 @ W2 ; CSR-gather+bias+relu -> a2
    {
        dim3 blk(D_H2, 256 / D_H2);
        k_linear<D_H1, D_H2><<<(N_NODES + blk.y - 1) / blk.y, blk>>>(ga1, W2, gt2);
        dim3 gblk(D_H2, 512 / D_H2);
        k_gather<D_H2><<<(N_NODES + gblk.y - 1) / gblk.y, gblk>>>(gt2, b2, ga2);
    }

    // decoder: out = a2 @ dec_W
    {
        dim3 blk(D_OUT, 256 / D_OUT);
        k_linear<D_H2, D_OUT><<<(N_NODES + blk.y - 1) / blk.y, blk>>>(ga2, decW, out);
    }
}

// round 11
// speedup vs baseline: 4.3202x; 1.0537x over previous
#include <cuda_runtime.h>
#include <cuda_fp16.h>
#include <math.h>
#include <stdint.h>

#define N_NODES 10000
#define N_EDGES 640000
#define D_IN    256
#define D_H1    64
#define D_H2    32
#define D_OUT   16

#define K_PAD   10016            // 313 * 32
#define M_PAD   10112            // 79 * 128
#define KT      313

// ---------------- scratch (device globals; no allocation allowed) ------------
__device__ __half g_Bh[(size_t)K_PAD * D_IN];    // fp16 emb, K-padded
__device__ float g_h [N_NODES * D_IN];
__device__ float g_t1[N_NODES * D_H1];
__device__ float g_a1[N_NODES * D_H1];
__device__ float g_t2[N_NODES * D_H2];
__device__ float g_a2[N_NODES * D_H2];
__device__ int   g_src[N_EDGES];
__device__ int   g_dst[N_EDGES];
__device__ int   g_csr_src[N_EDGES];
__device__ float g_csr_w[N_EDGES];
__device__ int   g_rowptr[N_NODES + 1];
__device__ int   g_cursor[N_NODES];
__device__ int   g_deg [N_NODES];
__device__ float g_dinv[N_NODES];
__device__ int   g_is64;

// ---------------- edge index dtype detection + decode (+deg count) -----------
__global__ void k_detect(const void* __restrict__ ei) {
    if (threadIdx.x == 0 && blockIdx.x == 0) {
        const long long* p = (const long long*)ei;
        int ok = 1;
        for (int i = 0; i < 16; i++) {
            long long v = p[i];
            if (v < 0 || v >= N_NODES) ok = 0;
        }
        g_is64 = ok;
    }
}

__global__ void k_decode_deg(const void* __restrict__ ei) {
    int e = blockIdx.x * blockDim.x + threadIdx.x;
    if (e >= N_EDGES) return;
    int s, d;
    if (g_is64) {
        const long long* p = (const long long*)ei;
        s = (int)p[e]; d = (int)p[N_EDGES + e];
    } else {
        const int* p = (const int*)ei;
        s = p[e]; d = p[N_EDGES + e];
    }
    g_src[e] = s;
    g_dst[e] = d;
    atomicAdd(&g_deg[d], 1);
}

// ---------------- CSR build: shfl scan + dinv ---------------------------------
__global__ __launch_bounds__(1024) void k_scan() {     // single block
    __shared__ int wsum[32];
    const int t    = threadIdx.x;
    const int lane = t & 31;
    const int wrp  = t >> 5;
    const int base = t * 10;
    int loc[10];
    int s = 0;
#pragma unroll
    for (int j = 0; j < 10; j++) {
        int i = base + j;
        int v = (i < N_NODES) ? g_deg[i] : 0;
        loc[j] = s;
        s += v;
        if (i < N_NODES) g_dinv[i] = rsqrtf((float)(v + 1));
    }
    // warp inclusive scan of s
    int inc = s;
#pragma unroll
    for (int off = 1; off < 32; off <<= 1) {
        int v = __shfl_up_sync(0xffffffffu, inc, off);
        if (lane >= off) inc += v;
    }
    if (lane == 31) wsum[wrp] = inc;
    __syncthreads();
    if (wrp == 0) {
        int v = wsum[lane];
        int wi = v;
#pragma unroll
        for (int off = 1; off < 32; off <<= 1) {
            int u = __shfl_up_sync(0xffffffffu, wi, off);
            if (lane >= off) wi += u;
        }
        wsum[lane] = wi - v;     // exclusive warp prefix
    }
    __syncthreads();
    int pre = wsum[wrp] + inc - s;   // exclusive prefix for this thread
#pragma unroll
    for (int j = 0; j < 10; j++) {
        int i = base + j;
        if (i < N_NODES) {
            g_rowptr[i] = pre + loc[j];
            g_cursor[i] = pre + loc[j];
        }
    }
    if (t == 1023) g_rowptr[N_NODES] = pre + s;
}

__global__ void k_fill_csr() {
    int e = blockIdx.x * blockDim.x + threadIdx.x;
    if (e >= N_EDGES) return;
    int s = g_src[e], d = g_dst[e];
    int pos = atomicAdd(&g_cursor[d], 1);
    g_csr_src[pos] = s;
    g_csr_w[pos]   = g_dinv[s];
}

// ---------------- fp16 prep for B (emb) ---------------------------------------
__global__ void k_prep_b(const float* __restrict__ emb) {
    int chunk = blockIdx.x * blockDim.x + threadIdx.x; // 8-half chunk
    if (chunk >= K_PAD * D_IN / 8) return;
    int row = chunk >> 5;
    int c   = chunk & 31;
    __half2 h[4];
    if (row < N_NODES) {
        const float4* p = (const float4*)&emb[(size_t)row * D_IN + c * 8];
        float4 v0 = p[0], v1 = p[1];
        h[0] = __floats2half2_rn(v0.x, v0.y);
        h[1] = __floats2half2_rn(v0.z, v0.w);
        h[2] = __floats2half2_rn(v1.x, v1.y);
        h[3] = __floats2half2_rn(v1.z, v1.w);
    } else {
        h[0] = h[1] = h[2] = h[3] = __floats2half2_rn(0.f, 0.f);
    }
    *(uint4*)&g_Bh[(size_t)row * D_IN + c * 8] = *(uint4*)h;
}

// ---------------- GEMM1 (fp16 HMMA, fp32 A staged + inline convert) -----------
// BM=128 BN=256 BK=32, 512 threads (16 warps = 4M x 4N), 4 smem stages.
// A staged as fp32 (cp.async, zero-fill tails); fragments built by LDS.64+cvt.
#define LDA_F 40                       // fp32 A stage stride (floats) — conflict-free
#define LDB_H 264
#define ASTG_F (128 * LDA_F)           // 5120 floats = 20480 B per stage
#define BSTG_H (32 * LDB_H)            // 8448 halfs  = 16896 B per stage
#define B_BYTE_OFF (4 * ASTG_F * 4)    // 81920
#define GEMM_SMEM (4 * ASTG_F * 4 + 4 * BSTG_H * 2)   // 149504 B

__device__ __forceinline__ uint32_t smem_u32(const void* p) {
    uint32_t a;
    asm("{ .reg .u64 t; cvta.to.shared.u64 t, %1; cvt.u32.u64 %0, t; }"
        : "=r"(a) : "l"(p));
    return a;
}
__device__ __forceinline__ void cp16(uint32_t dst, const void* src) {
    asm volatile("cp.async.cg.shared.global [%0], [%1], 16;" :: "r"(dst), "l"(src) : "memory");
}
__device__ __forceinline__ void cp16p(uint32_t dst, const void* src, bool valid) {
    int sz = valid ? 16 : 0;
    asm volatile("cp.async.cg.shared.global [%0], [%1], 16, %2;"
                 :: "r"(dst), "l"(src), "r"(sz) : "memory");
}
__device__ __forceinline__ void cp_commit() {
    asm volatile("cp.async.commit_group;" ::: "memory");
}
template <int NW>
__device__ __forceinline__ void cp_wait() {
    asm volatile("cp.async.wait_group %0;" :: "n"(NW) : "memory");
}
__device__ __forceinline__ void ldsm4t(uint32_t* r, uint32_t addr) {
    asm volatile("ldmatrix.sync.aligned.m8n8.x4.trans.shared.b16 {%0,%1,%2,%3}, [%4];"
                 : "=r"(r[0]), "=r"(r[1]), "=r"(r[2]), "=r"(r[3]) : "r"(addr));
}
__device__ __forceinline__ void mma_f16(float* c, const uint32_t* a, uint32_t b0, uint32_t b1) {
    asm volatile(
        "mma.sync.aligned.m16n8k16.row.col.f32.f16.f16.f32 "
        "{%0,%1,%2,%3}, {%4,%5,%6,%7}, {%8,%9}, {%0,%1,%2,%3};"
        : "+f"(c[0]), "+f"(c[1]), "+f"(c[2]), "+f"(c[3])
        : "r"(a[0]), "r"(a[1]), "r"(a[2]), "r"(a[3]), "r"(b0), "r"(b1));
}
__device__ __forceinline__ uint32_t packh2(float lo, float hi) {
    uint32_t r;
    asm("cvt.rn.f16x2.f32 %0, %1, %2;" : "=r"(r) : "f"(hi), "f"(lo));
    return r;
}

__global__ __launch_bounds__(512, 1)
void k_gemm1_f16(const float* __restrict__ X)   // x [10000,10000] fp32
{
    extern __shared__ float smf[];

    const int tid  = threadIdx.x;
    const int lane = tid & 31;
    const int wid  = tid >> 5;
    const int wm   = wid & 3;        // 0..3 (M)
    const int wn   = wid >> 2;       // 0..3 (N)
    const int m0   = blockIdx.x * 128;
    const uint32_t sbase = smem_u32(smf);

    float acc[2][8][4];
#pragma unroll
    for (int mi = 0; mi < 2; mi++)
#pragma unroll
        for (int ni = 0; ni < 8; ni++)
#pragma unroll
            for (int r = 0; r < 4; r++) acc[mi][ni][r] = 0.0f;

    // fill: A 1024 fp32 chunks (2/thread), B 1024 fp16 chunks (2/thread)
    auto fill = [&](int slot, int it) {
        const int k0 = it * 32;
#pragma unroll
        for (int i = 0; i < 2; i++) {
            int ch  = tid + i * 512;
            int row = ch >> 3, c4 = ch & 7;          // 8 chunks per 32-float row
            int gm  = m0 + row;
            int gk  = k0 + c4 * 4;
            bool v  = (gm < N_NODES) && (gk < N_NODES);
            const float* src = v ? &X[(size_t)gm * N_NODES + gk] : X;
            cp16p(sbase + (slot * ASTG_F + row * LDA_F + c4 * 4) * 4, src, v);
        }
#pragma unroll
        for (int i = 0; i < 2; i++) {
            int ch  = tid + i * 512;
            int row = ch >> 5, c = ch & 31;          // 32 chunks per 256-half row
            cp16(sbase + B_BYTE_OFF + (slot * BSTG_H + row * LDB_H) * 2 + c * 16,
                 &g_Bh[(size_t)(k0 + row) * D_IN + c * 8]);
        }
        cp_commit();
    };

    // A fragment source: float2 at staging[(wm*32+mi*16 + r)][ks*16 + 2c (+8)]
    const int a_r = lane >> 2;          // 0..7
    const int a_c = 2 * (lane & 3);     // 0,2,4,6
    const uint32_t b_lane_off = ((lane & 15) * LDB_H + (lane >> 4) * 8) * 2;

    auto compute = [&](int slot) {
        const float* stA = smf + slot * ASTG_F;
        const uint32_t bbase = sbase + B_BYTE_OFF + slot * (BSTG_H * 2);
#pragma unroll
        for (int ks = 0; ks < 2; ks++) {
            uint32_t a[2][4], b[4][4];
#pragma unroll
            for (int mi = 0; mi < 2; mi++) {
                const float* p = stA + (wm * 32 + mi * 16 + a_r) * LDA_F + ks * 16 + a_c;
                float2 v0 = *(const float2*)(p);
                float2 v1 = *(const float2*)(p + 8 * LDA_F);
                float2 v2 = *(const float2*)(p + 8);
                float2 v3 = *(const float2*)(p + 8 * LDA_F + 8);
                a[mi][0] = packh2(v0.x, v0.y);
                a[mi][1] = packh2(v1.x, v1.y);
                a[mi][2] = packh2(v2.x, v2.y);
                a[mi][3] = packh2(v3.x, v3.y);
            }
#pragma unroll
            for (int g = 0; g < 4; g++)
                ldsm4t(b[g], bbase + b_lane_off +
                             (ks * 16 * LDB_H + wn * 64 + g * 16) * 2);
#pragma unroll
            for (int mi = 0; mi < 2; mi++)
#pragma unroll
                for (int g = 0; g < 4; g++) {
                    mma_f16(acc[mi][g * 2 + 0], a[mi], b[g][0], b[g][1]);
                    mma_f16(acc[mi][g * 2 + 1], a[mi], b[g][2], b[g][3]);
                }
        }
    };

    // prologue: stages 0..2
    fill(0, 0);
    fill(1, 1);
    fill(2, 2);

    for (int it = 0; it < KT; ++it) {
        cp_wait<2>();
        __syncthreads();
        if (it + 3 < KT) fill((it + 3) & 3, it + 3);
        compute(it & 3);
    }

    // epilogue: relu + store
#pragma unroll
    for (int mi = 0; mi < 2; mi++) {
        int row0 = m0 + wm * 32 + mi * 16 + (lane >> 2);
#pragma unroll
        for (int ni = 0; ni < 8; ni++) {
            int col = wn * 64 + ni * 8 + (lane & 3) * 2;
            if (row0 < N_NODES) {
                float2 v = make_float2(fmaxf(acc[mi][ni][0], 0.f),
                                       fmaxf(acc[mi][ni][1], 0.f));
                *(float2*)&g_h[(size_t)row0 * D_IN + col] = v;
            }
            if (row0 + 8 < N_NODES) {
                float2 v = make_float2(fmaxf(acc[mi][ni][2], 0.f),
                                       fmaxf(acc[mi][ni][3], 0.f));
                *(float2*)&g_h[(size_t)(row0 + 8) * D_IN + col] = v;
            }
        }
    }
}

// ---------------- small dense linears: Y = X @ W -----------------------------
template <int IN, int OUT>
__global__ void k_linear(const float* __restrict__ X,
                         const float* __restrict__ W,
                         float* __restrict__ Y)
{
    int col = threadIdx.x;
    int row = blockIdx.x * blockDim.y + threadIdx.y;
    if (row >= N_NODES) return;
    const float* xr = X + (size_t)row * IN;
    float acc = 0.0f;
#pragma unroll 8
    for (int k = 0; k < IN; k++)
        acc = fmaf(xr[k], W[k * OUT + col], acc);
    Y[(size_t)row * OUT + col] = acc;
}

// ---------------- CSR gather aggregation + bias + relu ------------------------
template <int F>
__global__ void k_gather(const float* __restrict__ X,
                         const float* __restrict__ bias,
                         float* __restrict__ Y)
{
    int f = threadIdx.x;
    int i = blockIdx.x * blockDim.y + threadIdx.y;
    if (i >= N_NODES) return;
    int beg = g_rowptr[i], end = g_rowptr[i + 1];
    float di  = g_dinv[i];
    float acc = X[(size_t)i * F + f] * di;
    int j = beg;
    for (; j + 4 <= end; j += 4) {
        int   s0 = g_csr_src[j],     s1 = g_csr_src[j + 1];
        int   s2 = g_csr_src[j + 2], s3 = g_csr_src[j + 3];
        float w0 = g_csr_w[j],       w1 = g_csr_w[j + 1];
        float w2 = g_csr_w[j + 2],   w3 = g_csr_w[j + 3];
        acc = fmaf(X[(size_t)s0 * F + f], w0, acc);
        acc = fmaf(X[(size_t)s1 * F + f], w1, acc);
        acc = fmaf(X[(size_t)s2 * F + f], w2, acc);
        acc = fmaf(X[(size_t)s3 * F + f], w3, acc);
    }
    for (; j < end; j++)
        acc = fmaf(X[(size_t)g_csr_src[j] * F + f], g_csr_w[j], acc);
    Y[(size_t)i * F + f] = fmaxf(fmaf(acc, di, bias[f]), 0.0f);
}

// ---------------- launch -----------------------------------------------------
extern "C" void kernel_launch(void* const* d_in, const int* in_sizes, int n_in,
                              void* d_out, int out_size)
{
    const float* x    = (const float*)d_in[0];
    const void*  ei   = d_in[1];
    const float* emb  = (const float*)d_in[2];
    const float* W1   = (const float*)d_in[3];
    const float* b1   = (const float*)d_in[4];
    const float* W2   = (const float*)d_in[5];
    const float* b2   = (const float*)d_in[6];
    const float* decW = (const float*)d_in[7];
    float*       out  = (float*)d_out;

    float *gh, *gt1, *ga1, *gt2, *ga2;
    int* gdeg;
    cudaGetSymbolAddress((void**)&gh,  g_h);
    cudaGetSymbolAddress((void**)&gt1, g_t1);
    cudaGetSymbolAddress((void**)&ga1, g_a1);
    cudaGetSymbolAddress((void**)&gt2, g_t2);
    cudaGetSymbolAddress((void**)&ga2, g_a2);
    cudaGetSymbolAddress((void**)&gdeg, g_deg);

    cudaFuncSetAttribute(k_gemm1_f16, cudaFuncAttributeMaxDynamicSharedMemorySize, GEMM_SMEM);

    // graph structure: deg -> scan(+dinv) -> CSR
    cudaMemsetAsync(gdeg, 0, N_NODES * sizeof(int));
    k_detect<<<1, 32>>>(ei);
    k_decode_deg<<<(N_EDGES + 255) / 256, 256>>>(ei);
    k_scan<<<1, 1024>>>();
    k_fill_csr<<<(N_EDGES + 255) / 256, 256>>>();

    // fp16 prep for B only
    k_prep_b<<<(K_PAD * D_IN / 8 + 255) / 256, 256>>>(emb);

    // h = relu(x @ emb) — fp32 A consumed directly
    k_gemm1_f16<<<M_PAD / 128, 512, GEMM_SMEM>>>(x);

    // layer 1: t1 = h @ W1 ; CSR-gather+bias+relu -> a1
    {
        dim3 blk(D_H1, 256 / D_H1);
        k_linear<D_IN, D_H1><<<(N_NODES + blk.y - 1) / blk.y, blk>>>(gh, W1, gt1);
        dim3 gblk(D_H1, 512 / D_H1);
        k_gather<D_H1><<<(N_NODES + gblk.y - 1) / gblk.y, gblk>>>(gt1, b1, ga1);
    }

    // layer 2: t2 = a1 @ W2 ; CSR-gather+bias+relu -> a2
    {
        dim3 blk(D_H2, 256 / D_H2);
        k_linear<D_H1, D_H2><<<(N_NODES + blk.y - 1) / blk.y, blk>>>(ga1, W2, gt2);
        dim3 gblk(D_H2, 512 / D_H2);
        k_gather<D_H2><<<(N_NODES + gblk.y - 1) / gblk.y, gblk>>>(gt2, b2, ga2);
    }

    // decoder: out = a2 @ dec_W
    {
        dim3 blk(D_OUT, 256 / D_OUT);
        k_linear<D_H2, D_OUT><<<(N_NODES + blk.y - 1) / blk.y, blk>>>(ga2, decW, out);
    }
}

// round 12
// speedup vs baseline: 4.3214x; 1.0003x over previous
#include <cuda_runtime.h>
#include <cuda_fp16.h>
#include <math.h>
#include <stdint.h>

#define N_NODES 10000
#define N_EDGES 640000
#define D_IN    256
#define D_H1    64
#define D_H2    32
#define D_OUT   16

#define K_PAD   10016            // 313 * 32
#define M_PAD   10112            // 79 * 128
#define KT      313

// ---------------- scratch (device globals; no allocation allowed) ------------
__device__ __half g_Bh[(size_t)K_PAD * D_IN];    // fp16 emb, K-padded
__device__ float g_h [N_NODES * D_IN];
__device__ float g_t1[N_NODES * D_H1];
__device__ float g_a1[N_NODES * D_H1];
__device__ float g_t2[N_NODES * D_H2];
__device__ float g_a2[N_NODES * D_H2];
__device__ int   g_src[N_EDGES];
__device__ int   g_dst[N_EDGES];
__device__ int   g_csr_src[N_EDGES];
__device__ float g_csr_w[N_EDGES];
__device__ int   g_rowptr[N_NODES + 1];
__device__ int   g_cursor[N_NODES];
__device__ int   g_deg [N_NODES];
__device__ float g_dinv[N_NODES];
__device__ int   g_is64;

// ---------------- edge index dtype detection + decode (+deg count) -----------
__global__ void k_detect(const void* __restrict__ ei) {
    if (threadIdx.x == 0 && blockIdx.x == 0) {
        const long long* p = (const long long*)ei;
        int ok = 1;
        for (int i = 0; i < 16; i++) {
            long long v = p[i];
            if (v < 0 || v >= N_NODES) ok = 0;
        }
        g_is64 = ok;
    }
}

__global__ void k_decode_deg(const void* __restrict__ ei) {
    int e = blockIdx.x * blockDim.x + threadIdx.x;
    if (e >= N_EDGES) return;
    int s, d;
    if (g_is64) {
        const long long* p = (const long long*)ei;
        s = (int)p[e]; d = (int)p[N_EDGES + e];
    } else {
        const int* p = (const int*)ei;
        s = p[e]; d = p[N_EDGES + e];
    }
    g_src[e] = s;
    g_dst[e] = d;
    atomicAdd(&g_deg[d], 1);
}

// ---------------- CSR build: shfl scan + dinv ---------------------------------
__global__ __launch_bounds__(1024) void k_scan() {     // single block
    __shared__ int wsum[32];
    const int t    = threadIdx.x;
    const int lane = t & 31;
    const int wrp  = t >> 5;
    const int base = t * 10;
    int loc[10];
    int s = 0;
#pragma unroll
    for (int j = 0; j < 10; j++) {
        int i = base + j;
        int v = (i < N_NODES) ? g_deg[i] : 0;
        loc[j] = s;
        s += v;
        if (i < N_NODES) g_dinv[i] = rsqrtf((float)(v + 1));
    }
    // warp inclusive scan of s
    int inc = s;
#pragma unroll
    for (int off = 1; off < 32; off <<= 1) {
        int v = __shfl_up_sync(0xffffffffu, inc, off);
        if (lane >= off) inc += v;
    }
    if (lane == 31) wsum[wrp] = inc;
    __syncthreads();
    if (wrp == 0) {
        int v = wsum[lane];
        int wi = v;
#pragma unroll
        for (int off = 1; off < 32; off <<= 1) {
            int u = __shfl_up_sync(0xffffffffu, wi, off);
            if (lane >= off) wi += u;
        }
        wsum[lane] = wi - v;     // exclusive warp prefix
    }
    __syncthreads();
    int pre = wsum[wrp] + inc - s;   // exclusive prefix for this thread
#pragma unroll
    for (int j = 0; j < 10; j++) {
        int i = base + j;
        if (i < N_NODES) {
            g_rowptr[i] = pre + loc[j];
            g_cursor[i] = pre + loc[j];
        }
    }
    if (t == 1023) g_rowptr[N_NODES] = pre + s;
}

__global__ void k_fill_csr() {
    int e = blockIdx.x * blockDim.x + threadIdx.x;
    if (e >= N_EDGES) return;
    int s = g_src[e], d = g_dst[e];
    int pos = atomicAdd(&g_cursor[d], 1);
    g_csr_src[pos] = s;
    g_csr_w[pos]   = g_dinv[s];
}

// ---------------- fp16 prep for B (emb) ---------------------------------------
__global__ void k_prep_b(const float* __restrict__ emb) {
    int chunk = blockIdx.x * blockDim.x + threadIdx.x; // 8-half chunk
    if (chunk >= K_PAD * D_IN / 8) return;
    int row = chunk >> 5;
    int c   = chunk & 31;
    __half2 h[4];
    if (row < N_NODES) {
        const float4* p = (const float4*)&emb[(size_t)row * D_IN + c * 8];
        float4 v0 = p[0], v1 = p[1];
        h[0] = __floats2half2_rn(v0.x, v0.y);
        h[1] = __floats2half2_rn(v0.z, v0.w);
        h[2] = __floats2half2_rn(v1.x, v1.y);
        h[3] = __floats2half2_rn(v1.z, v1.w);
    } else {
        h[0] = h[1] = h[2] = h[3] = __floats2half2_rn(0.f, 0.f);
    }
    *(uint4*)&g_Bh[(size_t)row * D_IN + c * 8] = *(uint4*)h;
}

// ---------------- GEMM1 (fp16 HMMA, fp32 A staged + inline convert) -----------
// BM=128 BN=256 BK=32, 512 threads (16 warps = 4M x 4N), 4 smem stages.
// A staged as fp32 (cp.async, zero-fill tails); fragments built by LDS.64+cvt.
#define LDA_F 40                       // fp32 A stage stride (floats) — conflict-free
#define LDB_H 264
#define ASTG_F (128 * LDA_F)           // 5120 floats = 20480 B per stage
#define BSTG_H (32 * LDB_H)            // 8448 halfs  = 16896 B per stage
#define B_BYTE_OFF (4 * ASTG_F * 4)    // 81920
#define GEMM_SMEM (4 * ASTG_F * 4 + 4 * BSTG_H * 2)   // 149504 B

__device__ __forceinline__ uint32_t smem_u32(const void* p) {
    uint32_t a;
    asm("{ .reg .u64 t; cvta.to.shared.u64 t, %1; cvt.u32.u64 %0, t; }"
        : "=r"(a) : "l"(p));
    return a;
}
__device__ __forceinline__ void cp16(uint32_t dst, const void* src) {
    asm volatile("cp.async.cg.shared.global [%0], [%1], 16;" :: "r"(dst), "l"(src) : "memory");
}
__device__ __forceinline__ void cp16p(uint32_t dst, const void* src, bool valid) {
    int sz = valid ? 16 : 0;
    asm volatile("cp.async.cg.shared.global [%0], [%1], 16, %2;"
                 :: "r"(dst), "l"(src), "r"(sz) : "memory");
}
__device__ __forceinline__ void cp_commit() {
    asm volatile("cp.async.commit_group;" ::: "memory");
}
template <int NW>
__device__ __forceinline__ void cp_wait() {
    asm volatile("cp.async.wait_group %0;" :: "n"(NW) : "memory");
}
__device__ __forceinline__ void ldsm4t(uint32_t* r, uint32_t addr) {
    asm volatile("ldmatrix.sync.aligned.m8n8.x4.trans.shared.b16 {%0,%1,%2,%3}, [%4];"
                 : "=r"(r[0]), "=r"(r[1]), "=r"(r[2]), "=r"(r[3]) : "r"(addr));
}
__device__ __forceinline__ void mma_f16(float* c, const uint32_t* a, uint32_t b0, uint32_t b1) {
    asm volatile(
        "mma.sync.aligned.m16n8k16.row.col.f32.f16.f16.f32 "
        "{%0,%1,%2,%3}, {%4,%5,%6,%7}, {%8,%9}, {%0,%1,%2,%3};"
        : "+f"(c[0]), "+f"(c[1]), "+f"(c[2]), "+f"(c[3])
        : "r"(a[0]), "r"(a[1]), "r"(a[2]), "r"(a[3]), "r"(b0), "r"(b1));
}
__device__ __forceinline__ uint32_t packh2(float lo, float hi) {
    uint32_t r;
    asm("cvt.rn.f16x2.f32 %0, %1, %2;" : "=r"(r) : "f"(hi), "f"(lo));
    return r;
}

__global__ __launch_bounds__(512, 1)
void k_gemm1_f16(const float* __restrict__ X)   // x [10000,10000] fp32
{
    extern __shared__ float smf[];

    const int tid  = threadIdx.x;
    const int lane = tid & 31;
    const int wid  = tid >> 5;
    const int wm   = wid & 3;        // 0..3 (M)
    const int wn   = wid >> 2;       // 0..3 (N)
    const int m0   = blockIdx.x * 128;
    const uint32_t sbase = smem_u32(smf);

    float acc[2][8][4];
#pragma unroll
    for (int mi = 0; mi < 2; mi++)
#pragma unroll
        for (int ni = 0; ni < 8; ni++)
#pragma unroll
            for (int r = 0; r < 4; r++) acc[mi][ni][r] = 0.0f;

    // fill: A 1024 fp32 chunks (2/thread), B 1024 fp16 chunks (2/thread)
    auto fill = [&](int slot, int it) {
        const int k0 = it * 32;
#pragma unroll
        for (int i = 0; i < 2; i++) {
            int ch  = tid + i * 512;
            int row = ch >> 3, c4 = ch & 7;          // 8 chunks per 32-float row
            int gm  = m0 + row;
            int gk  = k0 + c4 * 4;
            bool v  = (gm < N_NODES) && (gk < N_NODES);
            const float* src = v ? &X[(size_t)gm * N_NODES + gk] : X;
            cp16p(sbase + (slot * ASTG_F + row * LDA_F + c4 * 4) * 4, src, v);
        }
#pragma unroll
        for (int i = 0; i < 2; i++) {
            int ch  = tid + i * 512;
            int row = ch >> 5, c = ch & 31;          // 32 chunks per 256-half row
            cp16(sbase + B_BYTE_OFF + (slot * BSTG_H + row * LDB_H) * 2 + c * 16,
                 &g_Bh[(size_t)(k0 + row) * D_IN + c * 8]);
        }
        cp_commit();
    };

    // A fragment source: float2 at staging[(wm*32+mi*16 + r)][ks*16 + 2c (+8)]
    const int a_r = lane >> 2;          // 0..7
    const int a_c = 2 * (lane & 3);     // 0,2,4,6
    const uint32_t b_lane_off = ((lane & 15) * LDB_H + (lane >> 4) * 8) * 2;

    auto compute = [&](int slot) {
        const float* stA = smf + slot * ASTG_F;
        const uint32_t bbase = sbase + B_BYTE_OFF + slot * (BSTG_H * 2);
#pragma unroll
        for (int ks = 0; ks < 2; ks++) {
            uint32_t a[2][4], b[4][4];
#pragma unroll
            for (int mi = 0; mi < 2; mi++) {
                const float* p = stA + (wm * 32 + mi * 16 + a_r) * LDA_F + ks * 16 + a_c;
                float2 v0 = *(const float2*)(p);
                float2 v1 = *(const float2*)(p + 8 * LDA_F);
                float2 v2 = *(const float2*)(p + 8);
                float2 v3 = *(const float2*)(p + 8 * LDA_F + 8);
                a[mi][0] = packh2(v0.x, v0.y);
                a[mi][1] = packh2(v1.x, v1.y);
                a[mi][2] = packh2(v2.x, v2.y);
                a[mi][3] = packh2(v3.x, v3.y);
            }
#pragma unroll
            for (int g = 0; g < 4; g++)
                ldsm4t(b[g], bbase + b_lane_off +
                             (ks * 16 * LDB_H + wn * 64 + g * 16) * 2);
#pragma unroll
            for (int mi = 0; mi < 2; mi++)
#pragma unroll
                for (int g = 0; g < 4; g++) {
                    mma_f16(acc[mi][g * 2 + 0], a[mi], b[g][0], b[g][1]);
                    mma_f16(acc[mi][g * 2 + 1], a[mi], b[g][2], b[g][3]);
                }
        }
    };

    // prologue: stages 0..2
    fill(0, 0);
    fill(1, 1);
    fill(2, 2);

    for (int it = 0; it < KT; ++it) {
        cp_wait<2>();
        __syncthreads();
        if (it + 3 < KT) fill((it + 3) & 3, it + 3);
        compute(it & 3);
    }

    // epilogue: relu + store
#pragma unroll
    for (int mi = 0; mi < 2; mi++) {
        int row0 = m0 + wm * 32 + mi * 16 + (lane >> 2);
#pragma unroll
        for (int ni = 0; ni < 8; ni++) {
            int col = wn * 64 + ni * 8 + (lane & 3) * 2;
            if (row0 < N_NODES) {
                float2 v = make_float2(fmaxf(acc[mi][ni][0], 0.f),
                                       fmaxf(acc[mi][ni][1], 0.f));
                *(float2*)&g_h[(size_t)row0 * D_IN + col] = v;
            }
            if (row0 + 8 < N_NODES) {
                float2 v = make_float2(fmaxf(acc[mi][ni][2], 0.f),
                                       fmaxf(acc[mi][ni][3], 0.f));
                *(float2*)&g_h[(size_t)(row0 + 8) * D_IN + col] = v;
            }
        }
    }
}

// ---------------- small dense linears: Y = X @ W -----------------------------
template <int IN, int OUT>
__global__ void k_linear(const float* __restrict__ X,
                         const float* __restrict__ W,
                         float* __restrict__ Y)
{
    int col = threadIdx.x;
    int row = blockIdx.x * blockDim.y + threadIdx.y;
    if (row >= N_NODES) return;
    const float* xr = X + (size_t)row * IN;
    float acc = 0.0f;
#pragma unroll 8
    for (int k = 0; k < IN; k++)
        acc = fmaf(xr[k], W[k * OUT + col], acc);
    Y[(size_t)row * OUT + col] = acc;
}

// ---------------- CSR gather aggregation + bias + relu ------------------------
template <int F>
__global__ void k_gather(const float* __restrict__ X,
                         const float* __restrict__ bias,
                         float* __restrict__ Y)
{
    int f = threadIdx.x;
    int i = blockIdx.x * blockDim.y + threadIdx.y;
    if (i >= N_NODES) return;
    int beg = g_rowptr[i], end = g_rowptr[i + 1];
    float di  = g_dinv[i];
    float acc = X[(size_t)i * F + f] * di;
    int j = beg;
    for (; j + 4 <= end; j += 4) {
        int   s0 = g_csr_src[j],     s1 = g_csr_src[j + 1];
        int   s2 = g_csr_src[j + 2], s3 = g_csr_src[j + 3];
        float w0 = g_csr_w[j],       w1 = g_csr_w[j + 1];
        float w2 = g_csr_w[j + 2],   w3 = g_csr_w[j + 3];
        acc = fmaf(X[(size_t)s0 * F + f], w0, acc);
        acc = fmaf(X[(size_t)s1 * F + f], w1, acc);
        acc = fmaf(X[(size_t)s2 * F + f], w2, acc);
        acc = fmaf(X[(size_t)s3 * F + f], w3, acc);
    }
    for (; j < end; j++)
        acc = fmaf(X[(size_t)g_csr_src[j] * F + f], g_csr_w[j], acc);
    Y[(size_t)i * F + f] = fmaxf(fmaf(acc, di, bias[f]), 0.0f);
}

// ---------------- launch -----------------------------------------------------
extern "C" void kernel_launch(void* const* d_in, const int* in_sizes, int n_in,
                              void* d_out, int out_size)
{
    const float* x    = (const float*)d_in[0];
    const void*  ei   = d_in[1];
    const float* emb  = (const float*)d_in[2];
    const float* W1   = (const float*)d_in[3];
    const float* b1   = (const float*)d_in[4];
    const float* W2   = (const float*)d_in[5];
    const float* b2   = (const float*)d_in[6];
    const float* decW = (const float*)d_in[7];
    float*       out  = (float*)d_out;

    float *gh, *gt1, *ga1, *gt2, *ga2;
    int* gdeg;
    cudaGetSymbolAddress((void**)&gh,  g_h);
    cudaGetSymbolAddress((void**)&gt1, g_t1);
    cudaGetSymbolAddress((void**)&ga1, g_a1);
    cudaGetSymbolAddress((void**)&gt2, g_t2);
    cudaGetSymbolAddress((void**)&ga2, g_a2);
    cudaGetSymbolAddress((void**)&gdeg, g_deg);

    cudaFuncSetAttribute(k_gemm1_f16, cudaFuncAttributeMaxDynamicSharedMemorySize, GEMM_SMEM);

    // graph structure: deg -> scan(+dinv) -> CSR
    cudaMemsetAsync(gdeg, 0, N_NODES * sizeof(int));
    k_detect<<<1, 32>>>(ei);
    k_decode_deg<<<(N_EDGES + 255) / 256, 256>>>(ei);
    k_scan<<<1, 1024>>>();
    k_fill_csr<<<(N_EDGES + 255) / 256, 256>>>();

    // fp16 prep for B only
    k_prep_b<<<(K_PAD * D_IN / 8 + 255) / 256, 256>>>(emb);

    // h = relu(x @ emb) — fp32 A consumed directly
    k_gemm1_f16<<<M_PAD / 128, 512, GEMM_SMEM>>>(x);

    // layer 1: t1 = h @ W1 ; CSR-gather+bias+relu -> a1
    {
        dim3 blk(D_H1, 256 / D_H1);
        k_linear<D_IN, D_H1><<<(N_NODES + blk.y - 1) / blk.y, blk>>>(gh, W1, gt1);
        dim3 gblk(D_H1, 512 / D_H1);
        k_gather<D_H1><<<(N_NODES + gblk.y - 1) / gblk.y, gblk>>>(gt1, b1, ga1);
    }

    // layer 2: t2 = a1 @ W2 ; CSR-gather+bias+relu -> a2
    {
        dim3 blk(D_H2, 256 / D_H2);
        k_linear<D_H1, D_H2><<<(N_NODES + blk.y - 1) / blk.y, blk>>>(ga1, W2, gt2);
        dim3 gblk(D_H2, 512 / D_H2);
        k_gather<D_H2><<<(N_NODES + gblk.y - 1) / gblk.y, gblk>>>(gt2, b2, ga2);
    }

    // decoder: out = a2 @ dec_W
    {
        dim3 blk(D_OUT, 256 / D_OUT);
        k_linear<D_H2, D_OUT><<<(N_NODES + blk.y - 1) / blk.y, blk>>>(ga2, decW, out);
    }
}

// round 13
// speedup vs baseline: 4.3259x; 1.0011x over previous
#include <cuda_runtime.h>
#include <cuda_fp16.h>
#include <math.h>
#include <stdint.h>

#define N_NODES 10000
#define N_EDGES 640000
#define D_IN    256
#define D_H1    64
#define D_H2    32
#define D_OUT   16

#define K_PAD   10016            // 313 * 32
#define M_PAD   10112            // 79 * 128
#define KT      313

// ---------------- scratch (device globals; no allocation allowed) ------------
__device__ __half g_Bh[(size_t)K_PAD * D_IN];    // fp16 emb, K-padded
__device__ float g_h [N_NODES * D_IN];
__device__ float g_t1[N_NODES * D_H1];
__device__ float g_a1[N_NODES * D_H1];
__device__ float g_t2[N_NODES * D_H2];
__device__ float g_a2[N_NODES * D_H2];
__device__ int   g_src[N_EDGES];
__device__ int   g_dst[N_EDGES];
__device__ int   g_csr_src[N_EDGES];
__device__ float g_csr_w[N_EDGES];
__device__ int   g_rowptr[N_NODES + 1];
__device__ int   g_cursor[N_NODES];
__device__ int   g_deg [N_NODES];
__device__ float g_dinv[N_NODES];
__device__ int   g_is64;

// ---------------- edge index dtype detection + decode (+deg count) -----------
__global__ void k_detect(const void* __restrict__ ei) {
    if (threadIdx.x == 0 && blockIdx.x == 0) {
        const long long* p = (const long long*)ei;
        int ok = 1;
        for (int i = 0; i < 16; i++) {
            long long v = p[i];
            if (v < 0 || v >= N_NODES) ok = 0;
        }
        g_is64 = ok;
    }
}

__global__ void k_decode_deg(const void* __restrict__ ei) {
    int e = blockIdx.x * blockDim.x + threadIdx.x;
    if (e >= N_EDGES) return;
    int s, d;
    if (g_is64) {
        const long long* p = (const long long*)ei;
        s = (int)p[e]; d = (int)p[N_EDGES + e];
    } else {
        const int* p = (const int*)ei;
        s = p[e]; d = p[N_EDGES + e];
    }
    g_src[e] = s;
    g_dst[e] = d;
    atomicAdd(&g_deg[d], 1);
}

// ---------------- CSR build: shfl scan + dinv ---------------------------------
__global__ __launch_bounds__(1024) void k_scan() {     // single block
    __shared__ int wsum[32];
    const int t    = threadIdx.x;
    const int lane = t & 31;
    const int wrp  = t >> 5;
    const int base = t * 10;
    int loc[10];
    int s = 0;
#pragma unroll
    for (int j = 0; j < 10; j++) {
        int i = base + j;
        int v = (i < N_NODES) ? g_deg[i] : 0;
        loc[j] = s;
        s += v;
        if (i < N_NODES) g_dinv[i] = rsqrtf((float)(v + 1));
    }
    // warp inclusive scan of s
    int inc = s;
#pragma unroll
    for (int off = 1; off < 32; off <<= 1) {
        int v = __shfl_up_sync(0xffffffffu, inc, off);
        if (lane >= off) inc += v;
    }
    if (lane == 31) wsum[wrp] = inc;
    __syncthreads();
    if (wrp == 0) {
        int v = wsum[lane];
        int wi = v;
#pragma unroll
        for (int off = 1; off < 32; off <<= 1) {
            int u = __shfl_up_sync(0xffffffffu, wi, off);
            if (lane >= off) wi += u;
        }
        wsum[lane] = wi - v;     // exclusive warp prefix
    }
    __syncthreads();
    int pre = wsum[wrp] + inc - s;   // exclusive prefix for this thread
#pragma unroll
    for (int j = 0; j < 10; j++) {
        int i = base + j;
        if (i < N_NODES) {
            g_rowptr[i] = pre + loc[j];
            g_cursor[i] = pre + loc[j];
        }
    }
    if (t == 1023) g_rowptr[N_NODES] = pre + s;
}

__global__ void k_fill_csr() {
    int e = blockIdx.x * blockDim.x + threadIdx.x;
    if (e >= N_EDGES) return;
    int s = g_src[e], d = g_dst[e];
    int pos = atomicAdd(&g_cursor[d], 1);
    g_csr_src[pos] = s;
    g_csr_w[pos]   = g_dinv[s];
}

// ---------------- fp16 prep for B (emb) ---------------------------------------
__global__ void k_prep_b(const float* __restrict__ emb) {
    int chunk = blockIdx.x * blockDim.x + threadIdx.x; // 8-half chunk
    if (chunk >= K_PAD * D_IN / 8) return;
    int row = chunk >> 5;
    int c   = chunk & 31;
    __half2 h[4];
    if (row < N_NODES) {
        const float4* p = (const float4*)&emb[(size_t)row * D_IN + c * 8];
        float4 v0 = p[0], v1 = p[1];
        h[0] = __floats2half2_rn(v0.x, v0.y);
        h[1] = __floats2half2_rn(v0.z, v0.w);
        h[2] = __floats2half2_rn(v1.x, v1.y);
        h[3] = __floats2half2_rn(v1.z, v1.w);
    } else {
        h[0] = h[1] = h[2] = h[3] = __floats2half2_rn(0.f, 0.f);
    }
    *(uint4*)&g_Bh[(size_t)row * D_IN + c * 8] = *(uint4*)h;
}

// ---------------- GEMM1 (fp16 HMMA, fp32 A staged + inline convert) -----------
// BM=128 BN=256 BK=32, 512 threads (16 warps = 4M x 4N), 4 smem stages.
// A staged as fp32 (cp.async, zero-fill tails); fragments built by LDS.64+cvt.
#define LDA_F 40                       // fp32 A stage stride (floats) — conflict-free
#define LDB_H 264
#define ASTG_F (128 * LDA_F)           // 5120 floats = 20480 B per stage
#define BSTG_H (32 * LDB_H)            // 8448 halfs  = 16896 B per stage
#define B_BYTE_OFF (4 * ASTG_F * 4)    // 81920
#define GEMM_SMEM (4 * ASTG_F * 4 + 4 * BSTG_H * 2)   // 149504 B

__device__ __forceinline__ uint32_t smem_u32(const void* p) {
    uint32_t a;
    asm("{ .reg .u64 t; cvta.to.shared.u64 t, %1; cvt.u32.u64 %0, t; }"
        : "=r"(a) : "l"(p));
    return a;
}
__device__ __forceinline__ void cp16(uint32_t dst, const void* src) {
    asm volatile("cp.async.cg.shared.global [%0], [%1], 16;" :: "r"(dst), "l"(src) : "memory");
}
__device__ __forceinline__ void cp16p(uint32_t dst, const void* src, bool valid) {
    int sz = valid ? 16 : 0;
    asm volatile("cp.async.cg.shared.global [%0], [%1], 16, %2;"
                 :: "r"(dst), "l"(src), "r"(sz) : "memory");
}
__device__ __forceinline__ void cp_commit() {
    asm volatile("cp.async.commit_group;" ::: "memory");
}
template <int NW>
__device__ __forceinline__ void cp_wait() {
    asm volatile("cp.async.wait_group %0;" :: "n"(NW) : "memory");
}
__device__ __forceinline__ void ldsm4t(uint32_t* r, uint32_t addr) {
    asm volatile("ldmatrix.sync.aligned.m8n8.x4.trans.shared.b16 {%0,%1,%2,%3}, [%4];"
                 : "=r"(r[0]), "=r"(r[1]), "=r"(r[2]), "=r"(r[3]) : "r"(addr));
}
__device__ __forceinline__ void mma_f16(float* c, const uint32_t* a, uint32_t b0, uint32_t b1) {
    asm volatile(
        "mma.sync.aligned.m16n8k16.row.col.f32.f16.f16.f32 "
        "{%0,%1,%2,%3}, {%4,%5,%6,%7}, {%8,%9}, {%0,%1,%2,%3};"
        : "+f"(c[0]), "+f"(c[1]), "+f"(c[2]), "+f"(c[3])
        : "r"(a[0]), "r"(a[1]), "r"(a[2]), "r"(a[3]), "r"(b0), "r"(b1));
}
__device__ __forceinline__ uint32_t packh2(float lo, float hi) {
    uint32_t r;
    asm("cvt.rn.f16x2.f32 %0, %1, %2;" : "=r"(r) : "f"(hi), "f"(lo));
    return r;
}

__global__ __launch_bounds__(512, 1)
void k_gemm1_f16(const float* __restrict__ X)   // x [10000,10000] fp32
{
    extern __shared__ float smf[];

    const int tid  = threadIdx.x;
    const int lane = tid & 31;
    const int wid  = tid >> 5;
    const int wm   = wid & 3;        // 0..3 (M)
    const int wn   = wid >> 2;       // 0..3 (N)
    const int m0   = blockIdx.x * 128;
    const uint32_t sbase = smem_u32(smf);

    float acc[2][8][4];
#pragma unroll
    for (int mi = 0; mi < 2; mi++)
#pragma unroll
        for (int ni = 0; ni < 8; ni++)
#pragma unroll
            for (int r = 0; r < 4; r++) acc[mi][ni][r] = 0.0f;

    // fill: A 1024 fp32 chunks (2/thread), B 1024 fp16 chunks (2/thread)
    auto fill = [&](int slot, int it) {
        const int k0 = it * 32;
#pragma unroll
        for (int i = 0; i < 2; i++) {
            int ch  = tid + i * 512;
            int row = ch >> 3, c4 = ch & 7;          // 8 chunks per 32-float row
            int gm  = m0 + row;
            int gk  = k0 + c4 * 4;
            bool v  = (gm < N_NODES) && (gk < N_NODES);
            const float* src = v ? &X[(size_t)gm * N_NODES + gk] : X;
            cp16p(sbase + (slot * ASTG_F + row * LDA_F + c4 * 4) * 4, src, v);
        }
#pragma unroll
        for (int i = 0; i < 2; i++) {
            int ch  = tid + i * 512;
            int row = ch >> 5, c = ch & 31;          // 32 chunks per 256-half row
            cp16(sbase + B_BYTE_OFF + (slot * BSTG_H + row * LDB_H) * 2 + c * 16,
                 &g_Bh[(size_t)(k0 + row) * D_IN + c * 8]);
        }
        cp_commit();
    };

    // A fragment source: float2 at staging[(wm*32+mi*16 + r)][ks*16 + 2c (+8)]
    const int a_r = lane >> 2;          // 0..7
    const int a_c = 2 * (lane & 3);     // 0,2,4,6
    const uint32_t b_lane_off = ((lane & 15) * LDB_H + (lane >> 4) * 8) * 2;

    auto compute = [&](int slot) {
        const float* stA = smf + slot * ASTG_F;
        const uint32_t bbase = sbase + B_BYTE_OFF + slot * (BSTG_H * 2);
#pragma unroll
        for (int ks = 0; ks < 2; ks++) {
            uint32_t a[2][4], b[4][4];
#pragma unroll
            for (int mi = 0; mi < 2; mi++) {
                const float* p = stA + (wm * 32 + mi * 16 + a_r) * LDA_F + ks * 16 + a_c;
                float2 v0 = *(const float2*)(p);
                float2 v1 = *(const float2*)(p + 8 * LDA_F);
                float2 v2 = *(const float2*)(p + 8);
                float2 v3 = *(const float2*)(p + 8 * LDA_F + 8);
                a[mi][0] = packh2(v0.x, v0.y);
                a[mi][1] = packh2(v1.x, v1.y);
                a[mi][2] = packh2(v2.x, v2.y);
                a[mi][3] = packh2(v3.x, v3.y);
            }
#pragma unroll
            for (int g = 0; g < 4; g++)
                ldsm4t(b[g], bbase + b_lane_off +
                             (ks * 16 * LDB_H + wn * 64 + g * 16) * 2);
#pragma unroll
            for (int mi = 0; mi < 2; mi++)
#pragma unroll
                for (int g = 0; g < 4; g++) {
                    mma_f16(acc[mi][g * 2 + 0], a[mi], b[g][0], b[g][1]);
                    mma_f16(acc[mi][g * 2 + 1], a[mi], b[g][2], b[g][3]);
                }
        }
    };

    // prologue: stages 0..2
    fill(0, 0);
    fill(1, 1);
    fill(2, 2);

    for (int it = 0; it < KT; ++it) {
        cp_wait<2>();
        __syncthreads();
        if (it + 3 < KT) fill((it + 3) & 3, it + 3);
        compute(it & 3);
    }

    // epilogue: relu + store
#pragma unroll
    for (int mi = 0; mi < 2; mi++) {
        int row0 = m0 + wm * 32 + mi * 16 + (lane >> 2);
#pragma unroll
        for (int ni = 0; ni < 8; ni++) {
            int col = wn * 64 + ni * 8 + (lane & 3) * 2;
            if (row0 < N_NODES) {
                float2 v = make_float2(fmaxf(acc[mi][ni][0], 0.f),
                                       fmaxf(acc[mi][ni][1], 0.f));
                *(float2*)&g_h[(size_t)row0 * D_IN + col] = v;
            }
            if (row0 + 8 < N_NODES) {
                float2 v = make_float2(fmaxf(acc[mi][ni][2], 0.f),
                                       fmaxf(acc[mi][ni][3], 0.f));
                *(float2*)&g_h[(size_t)(row0 + 8) * D_IN + col] = v;
            }
        }
    }
}

// ---------------- small dense linears: Y = X @ W -----------------------------
template <int IN, int OUT>
__global__ void k_linear(const float* __restrict__ X,
                         const float* __restrict__ W,
                         float* __restrict__ Y)
{
    int col = threadIdx.x;
    int row = blockIdx.x * blockDim.y + threadIdx.y;
    if (row >= N_NODES) return;
    const float* xr = X + (size_t)row * IN;
    float acc = 0.0f;
#pragma unroll 8
    for (int k = 0; k < IN; k++)
        acc = fmaf(xr[k], W[k * OUT + col], acc);
    Y[(size_t)row * OUT + col] = acc;
}

// ---------------- CSR gather aggregation + bias + relu ------------------------
template <int F>
__global__ void k_gather(const float* __restrict__ X,
                         const float* __restrict__ bias,
                         float* __restrict__ Y)
{
    int f = threadIdx.x;
    int i = blockIdx.x * blockDim.y + threadIdx.y;
    if (i >= N_NODES) return;
    int beg = g_rowptr[i], end = g_rowptr[i + 1];
    float di  = g_dinv[i];
    float acc = X[(size_t)i * F + f] * di;
    int j = beg;
    for (; j + 4 <= end; j += 4) {
        int   s0 = g_csr_src[j],     s1 = g_csr_src[j + 1];
        int   s2 = g_csr_src[j + 2], s3 = g_csr_src[j + 3];
        float w0 = g_csr_w[j],       w1 = g_csr_w[j + 1];
        float w2 = g_csr_w[j + 2],   w3 = g_csr_w[j + 3];
        acc = fmaf(X[(size_t)s0 * F + f], w0, acc);
        acc = fmaf(X[(size_t)s1 * F + f], w1, acc);
        acc = fmaf(X[(size_t)s2 * F + f], w2, acc);
        acc = fmaf(X[(size_t)s3 * F + f], w3, acc);
    }
    for (; j < end; j++)
        acc = fmaf(X[(size_t)g_csr_src[j] * F + f], g_csr_w[j], acc);
    Y[(size_t)i * F + f] = fmaxf(fmaf(acc, di, bias[f]), 0.0f);
}

// ---------------- launch -----------------------------------------------------
extern "C" void kernel_launch(void* const* d_in, const int* in_sizes, int n_in,
                              void* d_out, int out_size)
{
    const float* x    = (const float*)d_in[0];
    const void*  ei   = d_in[1];
    const float* emb  = (const float*)d_in[2];
    const float* W1   = (const float*)d_in[3];
    const float* b1   = (const float*)d_in[4];
    const float* W2   = (const float*)d_in[5];
    const float* b2   = (const float*)d_in[6];
    const float* decW = (const float*)d_in[7];
    float*       out  = (float*)d_out;

    float *gh, *gt1, *ga1, *gt2, *ga2;
    int* gdeg;
    cudaGetSymbolAddress((void**)&gh,  g_h);
    cudaGetSymbolAddress((void**)&gt1, g_t1);
    cudaGetSymbolAddress((void**)&ga1, g_a1);
    cudaGetSymbolAddress((void**)&gt2, g_t2);
    cudaGetSymbolAddress((void**)&ga2, g_a2);
    cudaGetSymbolAddress((void**)&gdeg, g_deg);

    cudaFuncSetAttribute(k_gemm1_f16, cudaFuncAttributeMaxDynamicSharedMemorySize, GEMM_SMEM);

    // graph structure: deg -> scan(+dinv) -> CSR
    cudaMemsetAsync(gdeg, 0, N_NODES * sizeof(int));
    k_detect<<<1, 32>>>(ei);
    k_decode_deg<<<(N_EDGES + 255) / 256, 256>>>(ei);
    k_scan<<<1, 1024>>>();
    k_fill_csr<<<(N_EDGES + 255) / 256, 256>>>();

    // fp16 prep for B only
    k_prep_b<<<(K_PAD * D_IN / 8 + 255) / 256, 256>>>(emb);

    // h = relu(x @ emb) — fp32 A consumed directly
    k_gemm1_f16<<<M_PAD / 128, 512, GEMM_SMEM>>>(x);

    // layer 1: t1 = h @ W1 ; CSR-gather+bias+relu -> a1
    {
        dim3 blk(D_H1, 256 / D_H1);
        k_linear<D_IN, D_H1><<<(N_NODES + blk.y - 1) / blk.y, blk>>>(gh, W1, gt1);
        dim3 gblk(D_H1, 512 / D_H1);
        k_gather<D_H1><<<(N_NODES + gblk.y - 1) / gblk.y, gblk>>>(gt1, b1, ga1);
    }

    // layer 2: t2 = a1 @ W2 ; CSR-gather+bias+relu -> a2
    {
        dim3 blk(D_H2, 256 / D_H2);
        k_linear<D_H1, D_H2><<<(N_NODES + blk.y - 1) / blk.y, blk>>>(ga1, W2, gt2);
        dim3 gblk(D_H2, 512 / D_H2);
        k_gather<D_H2><<<(N_NODES + gblk.y - 1) / gblk.y, gblk>>>(gt2, b2, ga2);
    }

    // decoder: out = a2 @ dec_W
    {
        dim3 blk(D_OUT, 256 / D_OUT);
        k_linear<D_H2, D_OUT><<<(N_NODES + blk.y - 1) / blk.y, blk>>>(ga2, decW, out);
    }
}